// round 1
// baseline (speedup 1.0000x reference)
#include <cuda_runtime.h>
#include <math.h>

// ---------------- problem constants ----------------
#define B_    2
#define S_    2048
#define DIN   2048
#define DOUT  2048
#define NH    16
#define HD    128
#define LAT   256
#define ROWS  (B_ * S_)            // 4096
#define ATT_SCALE 0.08838834764831845f   // 1/sqrt(128)

// ---------------- scratch (device globals: allocation-free) ----------------
__device__ float g_q[ROWS * DOUT];
__device__ float g_lat[ROWS * LAT];
__device__ float g_k[ROWS * DOUT];
__device__ float g_v[ROWS * DOUT];
__device__ float g_ctx[ROWS * DOUT];

// ====================================================================
// SGEMM: C[M,N] = A[M,K] @ B[K,N] (+ bias broadcast over rows)
// 128x128 block tile, BK=8, 256 threads, 8x8 per-thread micro-tile.
// Requires M%128==0, N%128==0, K%8==0 (true for all calls here).
// ====================================================================
__global__ __launch_bounds__(256) void sgemm128(
    const float* __restrict__ A, const float* __restrict__ Bm,
    float* __restrict__ C, const float* __restrict__ bias,
    int M, int N, int K)
{
    __shared__ float As[8][128];   // transposed: As[k][m]
    __shared__ float Bs[8][128];

    const int t  = threadIdx.x;
    const int bm = blockIdx.y * 128;
    const int bn = blockIdx.x * 128;
    const int tx = t & 15;         // 0..15 -> col group
    const int ty = t >> 4;         // 0..15 -> row group

    // load mapping
    const int arow = t >> 1;               // 0..127
    const int acol = (t & 1) * 4;          // 0 or 4
    const int brow = t >> 5;               // 0..7
    const int bcol = (t & 31) * 4;         // 0..124

    float acc[8][8];
#pragma unroll
    for (int i = 0; i < 8; i++)
#pragma unroll
        for (int j = 0; j < 8; j++) acc[i][j] = 0.f;

    const float* Aptr = A + (size_t)(bm + arow) * K + acol;
    const float* Bptr = Bm + (size_t)brow * N + bn + bcol;

    for (int k0 = 0; k0 < K; k0 += 8) {
        float4 av = *(const float4*)(Aptr + k0);
        As[acol + 0][arow] = av.x;
        As[acol + 1][arow] = av.y;
        As[acol + 2][arow] = av.z;
        As[acol + 3][arow] = av.w;
        float4 bv = *(const float4*)(Bptr + (size_t)k0 * N);
        *(float4*)&Bs[brow][bcol] = bv;
        __syncthreads();

#pragma unroll
        for (int kk = 0; kk < 8; kk++) {
            float a[8], b[8];
            *(float4*)(a + 0) = *(const float4*)&As[kk][ty * 8 + 0];
            *(float4*)(a + 4) = *(const float4*)&As[kk][ty * 8 + 4];
            *(float4*)(b + 0) = *(const float4*)&Bs[kk][tx * 8 + 0];
            *(float4*)(b + 4) = *(const float4*)&Bs[kk][tx * 8 + 4];
#pragma unroll
            for (int i = 0; i < 8; i++)
#pragma unroll
                for (int j = 0; j < 8; j++)
                    acc[i][j] += a[i] * b[j];
        }
        __syncthreads();
    }

#pragma unroll
    for (int i = 0; i < 8; i++) {
        int r = bm + ty * 8 + i;
#pragma unroll
        for (int j = 0; j < 8; j += 4) {
            int c = bn + tx * 8 + j;
            float4 o;
            o.x = acc[i][j + 0];
            o.y = acc[i][j + 1];
            o.z = acc[i][j + 2];
            o.w = acc[i][j + 3];
            if (bias) {
                o.x += bias[c + 0];
                o.y += bias[c + 1];
                o.z += bias[c + 2];
                o.w += bias[c + 3];
            }
            *(float4*)(C + (size_t)r * N + c) = o;
        }
    }
}

// ====================================================================
// Causal flash attention, fp32. One block = one (b,h, 64-row Q tile).
// 256 threads. Streaming softmax over 64-col K tiles.
// ====================================================================
#define FBM 64
#define FBN 64
// smem floats: Qs 64*128, Ks 64*129 (pad), Vs 64*128, Ss 64*65 (pad), stats 3*64
#define FA_SMEM_FLOATS (64*128 + 64*129 + 64*128 + 64*65 + 192)
#define FA_SMEM_BYTES  (FA_SMEM_FLOATS * 4)

__global__ __launch_bounds__(256) void flash_attn(
    const float* __restrict__ Qg, const float* __restrict__ Kg,
    const float* __restrict__ Vg, float* __restrict__ Ctx)
{
    extern __shared__ float sm[];
    float* Qs   = sm;                  // [64][128]
    float* Ks   = Qs + 64 * 128;       // [64][129]
    float* Vs   = Ks + 64 * 129;       // [64][128]
    float* Ss   = Vs + 64 * 128;       // [64][65]
    float* sm_m = Ss + 64 * 65;        // [64]
    float* sm_l = sm_m + 64;           // [64]
    float* sm_f = sm_l + 64;           // [64]

    const int t  = threadIdx.x;
    const int qb = blockIdx.x * FBM;
    const int bh = blockIdx.y;         // b*NH + h
    const int b  = bh >> 4;
    const int h  = bh & 15;

    const float* Qbase = Qg + (size_t)b * S_ * DOUT + (size_t)h * HD;
    const float* Kbase = Kg + (size_t)b * S_ * DOUT + (size_t)h * HD;
    const float* Vbase = Vg + (size_t)b * S_ * DOUT + (size_t)h * HD;

    // load Q tile (64 rows x 128 cols, row stride DOUT)
    for (int i = t; i < FBM * (HD / 4); i += 256) {
        int r  = i >> 5;           // /32
        int c4 = (i & 31) * 4;
        *(float4*)&Qs[r * HD + c4] =
            *(const float4*)(Qbase + (size_t)(qb + r) * DOUT + c4);
    }
    if (t < 64) { sm_m[t] = -INFINITY; sm_l[t] = 0.f; }

    float O[32];
#pragma unroll
    for (int j = 0; j < 32; j++) O[j] = 0.f;
    const int orow = t & 63;
    const int oc0  = (t >> 6) * 32;

    const int tr = t >> 4;   // 0..15
    const int tc = t & 15;   // 0..15

    const int nkt = qb / FBN + 1;   // causal: only tiles with kb <= qb+63
    for (int kt = 0; kt < nkt; kt++) {
        const int kb = kt * FBN;
        __syncthreads();   // previous iter's Ss/Vs reads done

        // load K (padded 129) and V (128) tiles
        for (int i = t; i < FBN * (HD / 4); i += 256) {
            int r  = i >> 5;
            int c4 = (i & 31) * 4;
            float4 kv = *(const float4*)(Kbase + (size_t)(kb + r) * DOUT + c4);
            Ks[r * 129 + c4 + 0] = kv.x;
            Ks[r * 129 + c4 + 1] = kv.y;
            Ks[r * 129 + c4 + 2] = kv.z;
            Ks[r * 129 + c4 + 3] = kv.w;
            *(float4*)&Vs[r * HD + c4] =
                *(const float4*)(Vbase + (size_t)(kb + r) * DOUT + c4);
        }
        __syncthreads();

        // scores: each thread computes a 4x4 block of the 64x64 tile
        float acc[4][4];
#pragma unroll
        for (int i = 0; i < 4; i++)
#pragma unroll
            for (int j = 0; j < 4; j++) acc[i][j] = 0.f;

        for (int d = 0; d < HD; d += 4) {
            float a[4][4], kb4[4][4];
#pragma unroll
            for (int i = 0; i < 4; i++)
                *(float4*)a[i] = *(const float4*)&Qs[(4 * tr + i) * HD + d];
#pragma unroll
            for (int j = 0; j < 4; j++) {
                int krow = (4 * tc + j) * 129 + d;
                kb4[j][0] = Ks[krow + 0];
                kb4[j][1] = Ks[krow + 1];
                kb4[j][2] = Ks[krow + 2];
                kb4[j][3] = Ks[krow + 3];
            }
#pragma unroll
            for (int i = 0; i < 4; i++)
#pragma unroll
                for (int j = 0; j < 4; j++)
#pragma unroll
                    for (int dd = 0; dd < 4; dd++)
                        acc[i][j] += a[i][dd] * kb4[j][dd];
        }

        // masked, scaled scores -> Ss
#pragma unroll
        for (int i = 0; i < 4; i++) {
            int qpos = qb + 4 * tr + i;
#pragma unroll
            for (int j = 0; j < 4; j++) {
                int kpos = kb + 4 * tc + j;
                float s = acc[i][j] * ATT_SCALE;
                Ss[(4 * tr + i) * 65 + 4 * tc + j] = (kpos > qpos) ? -INFINITY : s;
            }
        }
        __syncthreads();

        // per-row streaming softmax update (64 threads)
        if (t < 64) {
            float old_m = sm_m[t];
            float rmax = -INFINITY;
#pragma unroll 8
            for (int c = 0; c < 64; c++) rmax = fmaxf(rmax, Ss[t * 65 + c]);
            float nm = fmaxf(old_m, rmax);
            float f  = __expf(old_m - nm);
            float sum = 0.f;
#pragma unroll 8
            for (int c = 0; c < 64; c++) {
                float p = __expf(Ss[t * 65 + c] - nm);
                Ss[t * 65 + c] = p;
                sum += p;
            }
            sm_l[t] = sm_l[t] * f + sum;
            sm_m[t] = nm;
            sm_f[t] = f;
        }
        __syncthreads();

        // O update: each thread owns 1 row x 32 cols
        float f = sm_f[orow];
#pragma unroll
        for (int j = 0; j < 32; j++) O[j] *= f;
        for (int kk = 0; kk < 64; kk++) {
            float p = Ss[orow * 65 + kk];
            const float4* vrow = (const float4*)&Vs[kk * HD + oc0];
#pragma unroll
            for (int j4 = 0; j4 < 8; j4++) {
                float4 vv = vrow[j4];
                O[j4 * 4 + 0] += p * vv.x;
                O[j4 * 4 + 1] += p * vv.y;
                O[j4 * 4 + 2] += p * vv.z;
                O[j4 * 4 + 3] += p * vv.w;
            }
        }
    }

    // normalize + store ctx in [b, s, h*HD + c] layout
    float inv_l = 1.f / sm_l[orow];
    float* out = Ctx + ((size_t)b * S_ + qb + orow) * DOUT + (size_t)h * HD + oc0;
#pragma unroll
    for (int j4 = 0; j4 < 8; j4++) {
        float4 o;
        o.x = O[j4 * 4 + 0] * inv_l;
        o.y = O[j4 * 4 + 1] * inv_l;
        o.z = O[j4 * 4 + 2] * inv_l;
        o.w = O[j4 * 4 + 3] * inv_l;
        *(float4*)(out + j4 * 4) = o;
    }
}

// ====================================================================
// launch
// ====================================================================
extern "C" void kernel_launch(void* const* d_in, const int* in_sizes, int n_in,
                              void* d_out, int out_size)
{
    const float* x    = (const float*)d_in[0];
    const float* Wq   = (const float*)d_in[1];
    const float* Wdkv = (const float*)d_in[2];
    const float* Wuk  = (const float*)d_in[3];
    const float* Wuv  = (const float*)d_in[4];
    const float* Wout = (const float*)d_in[5];
    const float* bout = (const float*)d_in[6];
    float* out = (float*)d_out;

    float *q, *lat, *k, *v, *ctx;
    cudaGetSymbolAddress((void**)&q,   g_q);
    cudaGetSymbolAddress((void**)&lat, g_lat);
    cudaGetSymbolAddress((void**)&k,   g_k);
    cudaGetSymbolAddress((void**)&v,   g_v);
    cudaGetSymbolAddress((void**)&ctx, g_ctx);

    cudaFuncSetAttribute(flash_attn,
                         cudaFuncAttributeMaxDynamicSharedMemorySize,
                         FA_SMEM_BYTES);

    // q = x @ W_query                 [4096,2048] x [2048,2048]
    sgemm128<<<dim3(DOUT / 128, ROWS / 128), 256>>>(x, Wq, q, nullptr, ROWS, DOUT, DIN);
    // latent = x @ W_DKV              [4096,2048] x [2048,256]
    sgemm128<<<dim3(LAT / 128, ROWS / 128), 256>>>(x, Wdkv, lat, nullptr, ROWS, LAT, DIN);
    // k = latent @ W_UK               [4096,256] x [256,2048]
    sgemm128<<<dim3(DOUT / 128, ROWS / 128), 256>>>(lat, Wuk, k, nullptr, ROWS, DOUT, LAT);
    // v = latent @ W_UV
    sgemm128<<<dim3(DOUT / 128, ROWS / 128), 256>>>(lat, Wuv, v, nullptr, ROWS, DOUT, LAT);
    // attention -> ctx
    flash_attn<<<dim3(S_ / FBM, B_ * NH), 256, FA_SMEM_BYTES>>>(q, k, v, ctx);
    // out = ctx @ W_out + b_out
    sgemm128<<<dim3(DOUT / 128, ROWS / 128), 256>>>(ctx, Wout, out, bout, ROWS, DOUT, DOUT);
}

// round 2
// speedup vs baseline: 1.6677x; 1.6677x over previous
#include <cuda_runtime.h>
#include <math.h>
#include <stdint.h>

// ---------------- problem constants ----------------
#define B_    2
#define S_    2048
#define DIN   2048
#define DOUT  2048
#define NH    16
#define HD    128
#define LAT   256
#define ROWS  (B_ * S_)            // 4096
#define ATT_SCALE 0.08838834764831845f   // 1/sqrt(128)

// ---------------- scratch (device globals: allocation-free) ----------------
__device__ float g_q[ROWS * DOUT];
__device__ float g_lat[ROWS * LAT];
__device__ float g_k[ROWS * DOUT];
__device__ float g_v[ROWS * DOUT];
__device__ float g_ctx[ROWS * DOUT];

__device__ __forceinline__ uint32_t f2tf32(float x) {
    uint32_t r;
    asm("cvt.rna.tf32.f32 %0, %1;" : "=r"(r) : "f"(x));
    return r;
}

// ====================================================================
// TF32 tensor-core GEMM: C[M,N] = A[M,K] @ B[K,N] (+ optional bias)
// 128x128 block tile, BK=32, 256 threads (8 warps), warp tile 32x64,
// mma.sync.m16n8k8.tf32. Register-prefetch pipeline over K tiles.
// Requires M%128==0, N%128==0, K%32==0.
// Smem strides 36 / 136 -> conflict-free fragment loads.
// ====================================================================
#define AS_STRIDE 36
#define BS_STRIDE 136

__global__ __launch_bounds__(256) void tf32_gemm(
    const float* __restrict__ A, const float* __restrict__ Bm,
    float* __restrict__ C, const float* __restrict__ bias,
    int M, int N, int K)
{
    __shared__ uint32_t As[128 * AS_STRIDE];   // As[m][k], k-tile of 32
    __shared__ uint32_t Bs[32 * BS_STRIDE];    // Bs[k][n]

    const int t    = threadIdx.x;
    const int lane = t & 31;
    const int warp = t >> 5;
    const int bm   = blockIdx.y * 128;
    const int bn   = blockIdx.x * 128;

    // warp grid: 4 (m) x 2 (n); warp owns 32 rows x 64 cols
    const int wm = (warp >> 1) * 32;
    const int wn = (warp & 1) * 64;
    const int g  = lane >> 2;      // groupID 0..7
    const int tg = lane & 3;       // thread-in-group 0..3

    // global->smem load mapping
    const int arow = t >> 3;           // 0..31 (+32*i)
    const int acol = (t & 7) * 4;      // 0..28
    const int brow = t >> 5;           // 0..7 (+8*i)
    const int bcol = (t & 31) * 4;     // 0..124

    const float* Ag = A  + (size_t)(bm + arow) * K + acol;
    const float* Bg = Bm + (size_t)brow * N + bn + bcol;

    float acc[2][8][4];
#pragma unroll
    for (int mt = 0; mt < 2; mt++)
#pragma unroll
        for (int nt = 0; nt < 8; nt++)
#pragma unroll
            for (int r = 0; r < 4; r++) acc[mt][nt][r] = 0.f;

    float4 pa[4], pb[4];

#define LDAB(k0)                                                            \
    {                                                                       \
        _Pragma("unroll")                                                   \
        for (int i = 0; i < 4; i++)                                         \
            pa[i] = *(const float4*)(Ag + (size_t)(i * 32) * K + (k0));     \
        _Pragma("unroll")                                                   \
        for (int i = 0; i < 4; i++)                                         \
            pb[i] = *(const float4*)(Bg + (size_t)((k0) + i * 8) * N);      \
    }

#define STAB()                                                              \
    {                                                                       \
        _Pragma("unroll")                                                   \
        for (int i = 0; i < 4; i++) {                                       \
            uint32_t* p = &As[(arow + 32 * i) * AS_STRIDE + acol];          \
            uint4 v;                                                        \
            v.x = f2tf32(pa[i].x); v.y = f2tf32(pa[i].y);                   \
            v.z = f2tf32(pa[i].z); v.w = f2tf32(pa[i].w);                   \
            *(uint4*)p = v;                                                 \
        }                                                                   \
        _Pragma("unroll")                                                   \
        for (int i = 0; i < 4; i++) {                                       \
            uint32_t* p = &Bs[(brow + 8 * i) * BS_STRIDE + bcol];           \
            uint4 v;                                                        \
            v.x = f2tf32(pb[i].x); v.y = f2tf32(pb[i].y);                   \
            v.z = f2tf32(pb[i].z); v.w = f2tf32(pb[i].w);                   \
            *(uint4*)p = v;                                                 \
        }                                                                   \
    }

    const int nkt = K >> 5;

    LDAB(0);
    STAB();
    __syncthreads();

    for (int kt = 0; kt < nkt; kt++) {
        if (kt + 1 < nkt) LDAB((kt + 1) * 32);

#pragma unroll
        for (int k8 = 0; k8 < 32; k8 += 8) {
            uint32_t af[2][4];
            uint32_t bf[8][2];
#pragma unroll
            for (int mt = 0; mt < 2; mt++) {
                int mb = wm + mt * 16;
                af[mt][0] = As[(mb + g) * AS_STRIDE + k8 + tg];
                af[mt][1] = As[(mb + g + 8) * AS_STRIDE + k8 + tg];
                af[mt][2] = As[(mb + g) * AS_STRIDE + k8 + tg + 4];
                af[mt][3] = As[(mb + g + 8) * AS_STRIDE + k8 + tg + 4];
            }
#pragma unroll
            for (int nt = 0; nt < 8; nt++) {
                int nb = wn + nt * 8 + g;
                bf[nt][0] = Bs[(k8 + tg) * BS_STRIDE + nb];
                bf[nt][1] = Bs[(k8 + tg + 4) * BS_STRIDE + nb];
            }
#pragma unroll
            for (int mt = 0; mt < 2; mt++)
#pragma unroll
                for (int nt = 0; nt < 8; nt++) {
                    asm volatile(
                        "mma.sync.aligned.m16n8k8.row.col.f32.tf32.tf32.f32 "
                        "{%0,%1,%2,%3}, {%4,%5,%6,%7}, {%8,%9}, {%0,%1,%2,%3};"
                        : "+f"(acc[mt][nt][0]), "+f"(acc[mt][nt][1]),
                          "+f"(acc[mt][nt][2]), "+f"(acc[mt][nt][3])
                        : "r"(af[mt][0]), "r"(af[mt][1]),
                          "r"(af[mt][2]), "r"(af[mt][3]),
                          "r"(bf[nt][0]), "r"(bf[nt][1]));
                }
        }
        __syncthreads();
        if (kt + 1 < nkt) {
            STAB();
            __syncthreads();
        }
    }

    // epilogue
#pragma unroll
    for (int mt = 0; mt < 2; mt++) {
        int row0 = bm + wm + mt * 16 + g;
#pragma unroll
        for (int nt = 0; nt < 8; nt++) {
            int col = bn + wn + nt * 8 + tg * 2;
            float b0 = 0.f, b1 = 0.f;
            if (bias) { b0 = bias[col]; b1 = bias[col + 1]; }
            float2 v0, v1;
            v0.x = acc[mt][nt][0] + b0;
            v0.y = acc[mt][nt][1] + b1;
            v1.x = acc[mt][nt][2] + b0;
            v1.y = acc[mt][nt][3] + b1;
            *(float2*)(C + (size_t)row0 * N + col)       = v0;
            *(float2*)(C + (size_t)(row0 + 8) * N + col) = v1;
        }
    }
#undef LDAB
#undef STAB
}

// ====================================================================
// Causal flash attention, fp32. One block = one (b,h, 64-row Q tile).
// 256 threads. Streaming softmax over 64-col K tiles.
// ====================================================================
#define FBM 64
#define FBN 64
#define FA_SMEM_FLOATS (64*128 + 64*129 + 64*128 + 64*65 + 192)
#define FA_SMEM_BYTES  (FA_SMEM_FLOATS * 4)

__global__ __launch_bounds__(256) void flash_attn(
    const float* __restrict__ Qg, const float* __restrict__ Kg,
    const float* __restrict__ Vg, float* __restrict__ Ctx)
{
    extern __shared__ float sm[];
    float* Qs   = sm;                  // [64][128]
    float* Ks   = Qs + 64 * 128;       // [64][129]
    float* Vs   = Ks + 64 * 129;       // [64][128]
    float* Ss   = Vs + 64 * 128;       // [64][65]
    float* sm_m = Ss + 64 * 65;        // [64]
    float* sm_l = sm_m + 64;           // [64]
    float* sm_f = sm_l + 64;           // [64]

    const int t  = threadIdx.x;
    const int qb = blockIdx.x * FBM;
    const int bh = blockIdx.y;         // b*NH + h
    const int b  = bh >> 4;
    const int h  = bh & 15;

    const float* Qbase = Qg + (size_t)b * S_ * DOUT + (size_t)h * HD;
    const float* Kbase = Kg + (size_t)b * S_ * DOUT + (size_t)h * HD;
    const float* Vbase = Vg + (size_t)b * S_ * DOUT + (size_t)h * HD;

    for (int i = t; i < FBM * (HD / 4); i += 256) {
        int r  = i >> 5;
        int c4 = (i & 31) * 4;
        *(float4*)&Qs[r * HD + c4] =
            *(const float4*)(Qbase + (size_t)(qb + r) * DOUT + c4);
    }
    if (t < 64) { sm_m[t] = -INFINITY; sm_l[t] = 0.f; }

    float O[32];
#pragma unroll
    for (int j = 0; j < 32; j++) O[j] = 0.f;
    const int orow = t & 63;
    const int oc0  = (t >> 6) * 32;

    const int tr = t >> 4;   // 0..15
    const int tc = t & 15;   // 0..15

    const int nkt = qb / FBN + 1;
    for (int kt = 0; kt < nkt; kt++) {
        const int kb = kt * FBN;
        __syncthreads();

        for (int i = t; i < FBN * (HD / 4); i += 256) {
            int r  = i >> 5;
            int c4 = (i & 31) * 4;
            float4 kv = *(const float4*)(Kbase + (size_t)(kb + r) * DOUT + c4);
            Ks[r * 129 + c4 + 0] = kv.x;
            Ks[r * 129 + c4 + 1] = kv.y;
            Ks[r * 129 + c4 + 2] = kv.z;
            Ks[r * 129 + c4 + 3] = kv.w;
            *(float4*)&Vs[r * HD + c4] =
                *(const float4*)(Vbase + (size_t)(kb + r) * DOUT + c4);
        }
        __syncthreads();

        float acc[4][4];
#pragma unroll
        for (int i = 0; i < 4; i++)
#pragma unroll
            for (int j = 0; j < 4; j++) acc[i][j] = 0.f;

        for (int d = 0; d < HD; d += 4) {
            float a[4][4], kb4[4][4];
#pragma unroll
            for (int i = 0; i < 4; i++)
                *(float4*)a[i] = *(const float4*)&Qs[(4 * tr + i) * HD + d];
#pragma unroll
            for (int j = 0; j < 4; j++) {
                int krow = (4 * tc + j) * 129 + d;
                kb4[j][0] = Ks[krow + 0];
                kb4[j][1] = Ks[krow + 1];
                kb4[j][2] = Ks[krow + 2];
                kb4[j][3] = Ks[krow + 3];
            }
#pragma unroll
            for (int i = 0; i < 4; i++)
#pragma unroll
                for (int j = 0; j < 4; j++)
#pragma unroll
                    for (int dd = 0; dd < 4; dd++)
                        acc[i][j] += a[i][dd] * kb4[j][dd];
        }

#pragma unroll
        for (int i = 0; i < 4; i++) {
            int qpos = qb + 4 * tr + i;
#pragma unroll
            for (int j = 0; j < 4; j++) {
                int kpos = kb + 4 * tc + j;
                float s = acc[i][j] * ATT_SCALE;
                Ss[(4 * tr + i) * 65 + 4 * tc + j] = (kpos > qpos) ? -INFINITY : s;
            }
        }
        __syncthreads();

        if (t < 64) {
            float old_m = sm_m[t];
            float rmax = -INFINITY;
#pragma unroll 8
            for (int c = 0; c < 64; c++) rmax = fmaxf(rmax, Ss[t * 65 + c]);
            float nm = fmaxf(old_m, rmax);
            float f  = __expf(old_m - nm);
            float sum = 0.f;
#pragma unroll 8
            for (int c = 0; c < 64; c++) {
                float p = __expf(Ss[t * 65 + c] - nm);
                Ss[t * 65 + c] = p;
                sum += p;
            }
            sm_l[t] = sm_l[t] * f + sum;
            sm_m[t] = nm;
            sm_f[t] = f;
        }
        __syncthreads();

        float f = sm_f[orow];
#pragma unroll
        for (int j = 0; j < 32; j++) O[j] *= f;
        for (int kk = 0; kk < 64; kk++) {
            float p = Ss[orow * 65 + kk];
            const float4* vrow = (const float4*)&Vs[kk * HD + oc0];
#pragma unroll
            for (int j4 = 0; j4 < 8; j4++) {
                float4 vv = vrow[j4];
                O[j4 * 4 + 0] += p * vv.x;
                O[j4 * 4 + 1] += p * vv.y;
                O[j4 * 4 + 2] += p * vv.z;
                O[j4 * 4 + 3] += p * vv.w;
            }
        }
    }

    float inv_l = 1.f / sm_l[orow];
    float* out = Ctx + ((size_t)b * S_ + qb + orow) * DOUT + (size_t)h * HD + oc0;
#pragma unroll
    for (int j4 = 0; j4 < 8; j4++) {
        float4 o;
        o.x = O[j4 * 4 + 0] * inv_l;
        o.y = O[j4 * 4 + 1] * inv_l;
        o.z = O[j4 * 4 + 2] * inv_l;
        o.w = O[j4 * 4 + 3] * inv_l;
        *(float4*)(out + j4 * 4) = o;
    }
}

// ====================================================================
// launch
// ====================================================================
extern "C" void kernel_launch(void* const* d_in, const int* in_sizes, int n_in,
                              void* d_out, int out_size)
{
    const float* x    = (const float*)d_in[0];
    const float* Wq   = (const float*)d_in[1];
    const float* Wdkv = (const float*)d_in[2];
    const float* Wuk  = (const float*)d_in[3];
    const float* Wuv  = (const float*)d_in[4];
    const float* Wout = (const float*)d_in[5];
    const float* bout = (const float*)d_in[6];
    float* out = (float*)d_out;

    float *q, *lat, *k, *v, *ctx;
    cudaGetSymbolAddress((void**)&q,   g_q);
    cudaGetSymbolAddress((void**)&lat, g_lat);
    cudaGetSymbolAddress((void**)&k,   g_k);
    cudaGetSymbolAddress((void**)&v,   g_v);
    cudaGetSymbolAddress((void**)&ctx, g_ctx);

    cudaFuncSetAttribute(flash_attn,
                         cudaFuncAttributeMaxDynamicSharedMemorySize,
                         FA_SMEM_BYTES);

    // q = x @ W_query                 [4096,2048] x [2048,2048]
    tf32_gemm<<<dim3(DOUT / 128, ROWS / 128), 256>>>(x, Wq, q, nullptr, ROWS, DOUT, DIN);
    // latent = x @ W_DKV              [4096,2048] x [2048,256]
    tf32_gemm<<<dim3(LAT / 128, ROWS / 128), 256>>>(x, Wdkv, lat, nullptr, ROWS, LAT, DIN);
    // k = latent @ W_UK               [4096,256] x [256,2048]
    tf32_gemm<<<dim3(DOUT / 128, ROWS / 128), 256>>>(lat, Wuk, k, nullptr, ROWS, DOUT, LAT);
    // v = latent @ W_UV
    tf32_gemm<<<dim3(DOUT / 128, ROWS / 128), 256>>>(lat, Wuv, v, nullptr, ROWS, DOUT, LAT);
    // attention -> ctx
    flash_attn<<<dim3(S_ / FBM, B_ * NH), 256, FA_SMEM_BYTES>>>(q, k, v, ctx);
    // out = ctx @ W_out + b_out
    tf32_gemm<<<dim3(DOUT / 128, ROWS / 128), 256>>>(ctx, Wout, out, bout, ROWS, DOUT, DOUT);
}

// round 3
// speedup vs baseline: 2.0051x; 1.2023x over previous
#include <cuda_runtime.h>
#include <math.h>
#include <stdint.h>

// ---------------- problem constants ----------------
#define B_    2
#define S_    2048
#define DIN   2048
#define DOUT  2048
#define NH    16
#define HD    128
#define LAT   256
#define ROWS  (B_ * S_)            // 4096
#define ATT_SCALE 0.08838834764831845f   // 1/sqrt(128)

// ---------------- scratch (device globals: allocation-free) ----------------
__device__ float g_q[ROWS * DOUT];
__device__ float g_lat[ROWS * LAT];
__device__ float g_k[ROWS * DOUT];
__device__ float g_v[ROWS * DOUT];
__device__ float g_ctx[ROWS * DOUT];

__device__ __forceinline__ uint32_t f2tf32(float x) {
    uint32_t r;
    asm("cvt.rna.tf32.f32 %0, %1;" : "=r"(r) : "f"(x));
    return r;
}

// split x into tf32 hi + tf32 lo (error-compensated tf32x3)
__device__ __forceinline__ void split32(float x, uint32_t& h, uint32_t& l) {
    asm("cvt.rna.tf32.f32 %0, %1;" : "=r"(h) : "f"(x));
    float r = x - __uint_as_float(h);
    asm("cvt.rna.tf32.f32 %0, %1;" : "=r"(l) : "f"(r));
}

__device__ __forceinline__ void mma_tf32(float* d, const uint32_t* a, const uint32_t* b) {
    asm volatile(
        "mma.sync.aligned.m16n8k8.row.col.f32.tf32.tf32.f32 "
        "{%0,%1,%2,%3}, {%4,%5,%6,%7}, {%8,%9}, {%0,%1,%2,%3};"
        : "+f"(d[0]), "+f"(d[1]), "+f"(d[2]), "+f"(d[3])
        : "r"(a[0]), "r"(a[1]), "r"(a[2]), "r"(a[3]), "r"(b[0]), "r"(b[1]));
}

// ====================================================================
// TF32 tensor-core GEMM (unchanged from round 2)
// ====================================================================
#define AS_STRIDE 36
#define BS_STRIDE 136

__global__ __launch_bounds__(256) void tf32_gemm(
    const float* __restrict__ A, const float* __restrict__ Bm,
    float* __restrict__ C, const float* __restrict__ bias,
    int M, int N, int K)
{
    __shared__ uint32_t As[128 * AS_STRIDE];
    __shared__ uint32_t Bs[32 * BS_STRIDE];

    const int t    = threadIdx.x;
    const int lane = t & 31;
    const int warp = t >> 5;
    const int bm   = blockIdx.y * 128;
    const int bn   = blockIdx.x * 128;

    const int wm = (warp >> 1) * 32;
    const int wn = (warp & 1) * 64;
    const int g  = lane >> 2;
    const int tg = lane & 3;

    const int arow = t >> 3;
    const int acol = (t & 7) * 4;
    const int brow = t >> 5;
    const int bcol = (t & 31) * 4;

    const float* Ag = A  + (size_t)(bm + arow) * K + acol;
    const float* Bg = Bm + (size_t)brow * N + bn + bcol;

    float acc[2][8][4];
#pragma unroll
    for (int mt = 0; mt < 2; mt++)
#pragma unroll
        for (int nt = 0; nt < 8; nt++)
#pragma unroll
            for (int r = 0; r < 4; r++) acc[mt][nt][r] = 0.f;

    float4 pa[4], pb[4];

#define LDAB(k0)                                                            \
    {                                                                       \
        _Pragma("unroll")                                                   \
        for (int i = 0; i < 4; i++)                                         \
            pa[i] = *(const float4*)(Ag + (size_t)(i * 32) * K + (k0));     \
        _Pragma("unroll")                                                   \
        for (int i = 0; i < 4; i++)                                         \
            pb[i] = *(const float4*)(Bg + (size_t)((k0) + i * 8) * N);      \
    }

#define STAB()                                                              \
    {                                                                       \
        _Pragma("unroll")                                                   \
        for (int i = 0; i < 4; i++) {                                       \
            uint32_t* p = &As[(arow + 32 * i) * AS_STRIDE + acol];          \
            uint4 v;                                                        \
            v.x = f2tf32(pa[i].x); v.y = f2tf32(pa[i].y);                   \
            v.z = f2tf32(pa[i].z); v.w = f2tf32(pa[i].w);                   \
            *(uint4*)p = v;                                                 \
        }                                                                   \
        _Pragma("unroll")                                                   \
        for (int i = 0; i < 4; i++) {                                       \
            uint32_t* p = &Bs[(brow + 8 * i) * BS_STRIDE + bcol];           \
            uint4 v;                                                        \
            v.x = f2tf32(pb[i].x); v.y = f2tf32(pb[i].y);                   \
            v.z = f2tf32(pb[i].z); v.w = f2tf32(pb[i].w);                   \
            *(uint4*)p = v;                                                 \
        }                                                                   \
    }

    const int nkt = K >> 5;

    LDAB(0);
    STAB();
    __syncthreads();

    for (int kt = 0; kt < nkt; kt++) {
        if (kt + 1 < nkt) LDAB((kt + 1) * 32);

#pragma unroll
        for (int k8 = 0; k8 < 32; k8 += 8) {
            uint32_t af[2][4];
            uint32_t bf[8][2];
#pragma unroll
            for (int mt = 0; mt < 2; mt++) {
                int mb = wm + mt * 16;
                af[mt][0] = As[(mb + g) * AS_STRIDE + k8 + tg];
                af[mt][1] = As[(mb + g + 8) * AS_STRIDE + k8 + tg];
                af[mt][2] = As[(mb + g) * AS_STRIDE + k8 + tg + 4];
                af[mt][3] = As[(mb + g + 8) * AS_STRIDE + k8 + tg + 4];
            }
#pragma unroll
            for (int nt = 0; nt < 8; nt++) {
                int nb = wn + nt * 8 + g;
                bf[nt][0] = Bs[(k8 + tg) * BS_STRIDE + nb];
                bf[nt][1] = Bs[(k8 + tg + 4) * BS_STRIDE + nb];
            }
#pragma unroll
            for (int mt = 0; mt < 2; mt++)
#pragma unroll
                for (int nt = 0; nt < 8; nt++)
                    mma_tf32(acc[mt][nt], af[mt], bf[nt]);
        }
        __syncthreads();
        if (kt + 1 < nkt) {
            STAB();
            __syncthreads();
        }
    }

#pragma unroll
    for (int mt = 0; mt < 2; mt++) {
        int row0 = bm + wm + mt * 16 + g;
#pragma unroll
        for (int nt = 0; nt < 8; nt++) {
            int col = bn + wn + nt * 8 + tg * 2;
            float b0 = 0.f, b1 = 0.f;
            if (bias) { b0 = bias[col]; b1 = bias[col + 1]; }
            float2 v0, v1;
            v0.x = acc[mt][nt][0] + b0;
            v0.y = acc[mt][nt][1] + b1;
            v1.x = acc[mt][nt][2] + b0;
            v1.y = acc[mt][nt][3] + b1;
            *(float2*)(C + (size_t)row0 * N + col)       = v0;
            *(float2*)(C + (size_t)(row0 + 8) * N + col) = v1;
        }
    }
#undef LDAB
#undef STAB
}

// ====================================================================
// Tensor-core causal flash attention, tf32x3 (~fp32 accurate).
// Block = 256 threads (8 warps). Q tile 128 rows, K/V tile 32 rows.
// Warp w owns S/O rows [16w, 16w+16). Softmax in registers+shuffles.
// K/V pre-split hi/lo into smem once per tile (interleaved u32 pairs).
// ====================================================================
#define FBM 128
#define FBN 32
#define QS_STRIDE  132
#define KS2_STRIDE 264
#define VS2_STRIDE 264
#define PS_STRIDE  36
#define FA_SMEM_BYTES ((128*QS_STRIDE + FBN*KS2_STRIDE + FBN*VS2_STRIDE + 128*PS_STRIDE) * 4)

__global__ __launch_bounds__(256) void flash_attn_tc(
    const float* __restrict__ Qg, const float* __restrict__ Kg,
    const float* __restrict__ Vg, float* __restrict__ Ctx)
{
    extern __shared__ float smf[];
    float*    Qs  = smf;                                  // [128][132] fp32
    uint32_t* Ks2 = (uint32_t*)(Qs + 128 * QS_STRIDE);    // [32][264] {hi,lo}
    uint32_t* Vs2 = Ks2 + FBN * KS2_STRIDE;               // [32][264] {hi,lo}
    float*    Ps  = (float*)(Vs2 + FBN * VS2_STRIDE);     // [128][36] fp32

    const int t    = threadIdx.x;
    const int lane = t & 31;
    const int warp = t >> 5;
    const int g    = lane >> 2;
    const int tg   = lane & 3;

    // longest blocks (largest qb) first to shrink the wave tail
    const int qt = gridDim.x - 1 - blockIdx.x;
    const int qb = qt * FBM;
    const int bh = blockIdx.y;
    const int b  = bh >> 4;
    const int h  = bh & 15;

    const float* Qbase = Qg + (size_t)b * S_ * DOUT + (size_t)h * HD;
    const float* Kbase = Kg + (size_t)b * S_ * DOUT + (size_t)h * HD;
    const float* Vbase = Vg + (size_t)b * S_ * DOUT + (size_t)h * HD;

    // load Q tile (fp32)
    for (int i = t; i < FBM * (HD / 4); i += 256) {
        int r  = i >> 5;
        int c4 = (i & 31) * 4;
        *(float4*)&Qs[r * QS_STRIDE + c4] =
            *(const float4*)(Qbase + (size_t)(qb + r) * DOUT + c4);
    }

    float oacc[16][4];
#pragma unroll
    for (int nt = 0; nt < 16; nt++)
#pragma unroll
        for (int r = 0; r < 4; r++) oacc[nt][r] = 0.f;

    float m0 = -INFINITY, m1 = -INFINITY, l0 = 0.f, l1 = 0.f;
    const int r0 = qb + warp * 16 + g;
    const int r1 = r0 + 8;
    const int qrow0 = (warp * 16 + g) * QS_STRIDE;
    const int qrow1 = qrow0 + 8 * QS_STRIDE;
    const int prow0 = (warp * 16 + g) * PS_STRIDE;
    const int prow1 = prow0 + 8 * PS_STRIDE;

    const int nkt = qb / FBN + 4;   // causal: cover cols up to qb+127
    for (int kt = 0; kt < nkt; kt++) {
        const int kb = kt * FBN;
        __syncthreads();   // all warps done with previous Ks2/Vs2

        // load K,V tile; split to {hi,lo} pairs
        for (int i = t; i < FBN * (HD / 4); i += 256) {
            int r  = i >> 5;
            int c4 = (i & 31) * 4;
            float4 kv = *(const float4*)(Kbase + (size_t)(kb + r) * DOUT + c4);
            uint4 pk0, pk1;
            split32(kv.x, pk0.x, pk0.y); split32(kv.y, pk0.z, pk0.w);
            split32(kv.z, pk1.x, pk1.y); split32(kv.w, pk1.z, pk1.w);
            *(uint4*)&Ks2[r * KS2_STRIDE + 2 * c4]     = pk0;
            *(uint4*)&Ks2[r * KS2_STRIDE + 2 * c4 + 4] = pk1;
            float4 vv = *(const float4*)(Vbase + (size_t)(kb + r) * DOUT + c4);
            split32(vv.x, pk0.x, pk0.y); split32(vv.y, pk0.z, pk0.w);
            split32(vv.z, pk1.x, pk1.y); split32(vv.w, pk1.z, pk1.w);
            *(uint4*)&Vs2[r * VS2_STRIDE + 2 * c4]     = pk0;
            *(uint4*)&Vs2[r * VS2_STRIDE + 2 * c4 + 4] = pk1;
        }
        __syncthreads();

        // ---- S = Q K^T (tf32x3), warp tile 16x32 ----
        float sacc[4][4];
#pragma unroll
        for (int nt = 0; nt < 4; nt++)
#pragma unroll
            for (int r = 0; r < 4; r++) sacc[nt][r] = 0.f;

#pragma unroll
        for (int k8 = 0; k8 < HD; k8 += 8) {
            uint32_t ah[4], al[4];
            split32(Qs[qrow0 + k8 + tg],     ah[0], al[0]);
            split32(Qs[qrow1 + k8 + tg],     ah[1], al[1]);
            split32(Qs[qrow0 + k8 + tg + 4], ah[2], al[2]);
            split32(Qs[qrow1 + k8 + tg + 4], ah[3], al[3]);
#pragma unroll
            for (int nt = 0; nt < 4; nt++) {
                uint2 b0 = *(const uint2*)&Ks2[(nt * 8 + g) * KS2_STRIDE + 2 * (k8 + tg)];
                uint2 b1 = *(const uint2*)&Ks2[(nt * 8 + g) * KS2_STRIDE + 2 * (k8 + tg + 4)];
                uint32_t bhi[2] = {b0.x, b1.x};
                uint32_t blo[2] = {b0.y, b1.y};
                mma_tf32(sacc[nt], ah, bhi);
                mma_tf32(sacc[nt], al, bhi);
                mma_tf32(sacc[nt], ah, blo);
            }
        }

        // ---- scale + causal mask ----
        const bool need_mask = (kb + FBN - 1 > qb);
#pragma unroll
        for (int nt = 0; nt < 4; nt++) {
            sacc[nt][0] *= ATT_SCALE;
            sacc[nt][1] *= ATT_SCALE;
            sacc[nt][2] *= ATT_SCALE;
            sacc[nt][3] *= ATT_SCALE;
            if (need_mask) {
                int c0 = kb + nt * 8 + 2 * tg;
                int c1 = c0 + 1;
                if (c0 > r0) sacc[nt][0] = -INFINITY;
                if (c1 > r0) sacc[nt][1] = -INFINITY;
                if (c0 > r1) sacc[nt][2] = -INFINITY;
                if (c1 > r1) sacc[nt][3] = -INFINITY;
            }
        }

        // ---- online softmax (rows r0, r1 live in this warp's 4-lane groups) ----
        float mx0 = -INFINITY, mx1 = -INFINITY;
#pragma unroll
        for (int nt = 0; nt < 4; nt++) {
            mx0 = fmaxf(mx0, fmaxf(sacc[nt][0], sacc[nt][1]));
            mx1 = fmaxf(mx1, fmaxf(sacc[nt][2], sacc[nt][3]));
        }
        mx0 = fmaxf(mx0, __shfl_xor_sync(0xffffffffu, mx0, 1));
        mx0 = fmaxf(mx0, __shfl_xor_sync(0xffffffffu, mx0, 2));
        mx1 = fmaxf(mx1, __shfl_xor_sync(0xffffffffu, mx1, 1));
        mx1 = fmaxf(mx1, __shfl_xor_sync(0xffffffffu, mx1, 2));

        float nm0 = fmaxf(m0, mx0), nm1 = fmaxf(m1, mx1);
        float f0 = __expf(m0 - nm0), f1 = __expf(m1 - nm1);
        m0 = nm0; m1 = nm1;

        float s0 = 0.f, s1 = 0.f;
#pragma unroll
        for (int nt = 0; nt < 4; nt++) {
            float p0 = __expf(sacc[nt][0] - nm0);
            float p1 = __expf(sacc[nt][1] - nm0);
            float p2 = __expf(sacc[nt][2] - nm1);
            float p3 = __expf(sacc[nt][3] - nm1);
            s0 += p0 + p1;
            s1 += p2 + p3;
            *(float2*)&Ps[prow0 + nt * 8 + 2 * tg] = make_float2(p0, p1);
            *(float2*)&Ps[prow1 + nt * 8 + 2 * tg] = make_float2(p2, p3);
        }
        s0 += __shfl_xor_sync(0xffffffffu, s0, 1);
        s0 += __shfl_xor_sync(0xffffffffu, s0, 2);
        s1 += __shfl_xor_sync(0xffffffffu, s1, 1);
        s1 += __shfl_xor_sync(0xffffffffu, s1, 2);
        l0 = l0 * f0 + s0;
        l1 = l1 * f1 + s1;

#pragma unroll
        for (int nt = 0; nt < 16; nt++) {
            oacc[nt][0] *= f0;
            oacc[nt][1] *= f0;
            oacc[nt][2] *= f1;
            oacc[nt][3] *= f1;
        }
        __syncwarp();

        // ---- O += P V (tf32x3), warp tile 16x128, k = 32 ----
#pragma unroll
        for (int k8 = 0; k8 < FBN; k8 += 8) {
            uint32_t ah[4], al[4];
            split32(Ps[prow0 + k8 + tg],     ah[0], al[0]);
            split32(Ps[prow1 + k8 + tg],     ah[1], al[1]);
            split32(Ps[prow0 + k8 + tg + 4], ah[2], al[2]);
            split32(Ps[prow1 + k8 + tg + 4], ah[3], al[3]);
#pragma unroll
            for (int nt = 0; nt < 16; nt++) {
                uint2 b0 = *(const uint2*)&Vs2[(k8 + tg) * VS2_STRIDE + 2 * (nt * 8 + g)];
                uint2 b1 = *(const uint2*)&Vs2[(k8 + tg + 4) * VS2_STRIDE + 2 * (nt * 8 + g)];
                uint32_t bhi[2] = {b0.x, b1.x};
                uint32_t blo[2] = {b0.y, b1.y};
                mma_tf32(oacc[nt], ah, bhi);
                mma_tf32(oacc[nt], al, bhi);
                mma_tf32(oacc[nt], ah, blo);
            }
        }
    }

    // ---- epilogue: normalize and store ----
    float inv0 = 1.f / l0, inv1 = 1.f / l1;
    float* out0 = Ctx + ((size_t)b * S_ + r0) * DOUT + (size_t)h * HD;
    float* out1 = Ctx + ((size_t)b * S_ + r1) * DOUT + (size_t)h * HD;
#pragma unroll
    for (int nt = 0; nt < 16; nt++) {
        int c = nt * 8 + 2 * tg;
        *(float2*)(out0 + c) = make_float2(oacc[nt][0] * inv0, oacc[nt][1] * inv0);
        *(float2*)(out1 + c) = make_float2(oacc[nt][2] * inv1, oacc[nt][3] * inv1);
    }
}

// ====================================================================
// launch
// ====================================================================
extern "C" void kernel_launch(void* const* d_in, const int* in_sizes, int n_in,
                              void* d_out, int out_size)
{
    const float* x    = (const float*)d_in[0];
    const float* Wq   = (const float*)d_in[1];
    const float* Wdkv = (const float*)d_in[2];
    const float* Wuk  = (const float*)d_in[3];
    const float* Wuv  = (const float*)d_in[4];
    const float* Wout = (const float*)d_in[5];
    const float* bout = (const float*)d_in[6];
    float* out = (float*)d_out;

    float *q, *lat, *k, *v, *ctx;
    cudaGetSymbolAddress((void**)&q,   g_q);
    cudaGetSymbolAddress((void**)&lat, g_lat);
    cudaGetSymbolAddress((void**)&k,   g_k);
    cudaGetSymbolAddress((void**)&v,   g_v);
    cudaGetSymbolAddress((void**)&ctx, g_ctx);

    cudaFuncSetAttribute(flash_attn_tc,
                         cudaFuncAttributeMaxDynamicSharedMemorySize,
                         FA_SMEM_BYTES);

    tf32_gemm<<<dim3(DOUT / 128, ROWS / 128), 256>>>(x, Wq, q, nullptr, ROWS, DOUT, DIN);
    tf32_gemm<<<dim3(LAT / 128, ROWS / 128), 256>>>(x, Wdkv, lat, nullptr, ROWS, LAT, DIN);
    tf32_gemm<<<dim3(DOUT / 128, ROWS / 128), 256>>>(lat, Wuk, k, nullptr, ROWS, DOUT, LAT);
    tf32_gemm<<<dim3(DOUT / 128, ROWS / 128), 256>>>(lat, Wuv, v, nullptr, ROWS, DOUT, LAT);
    flash_attn_tc<<<dim3(S_ / FBM, B_ * NH), 256, FA_SMEM_BYTES>>>(q, k, v, ctx);
    tf32_gemm<<<dim3(DOUT / 128, ROWS / 128), 256>>>(ctx, Wout, out, bout, ROWS, DOUT, DOUT);
}

// round 4
// speedup vs baseline: 2.5359x; 1.2647x over previous
#include <cuda_runtime.h>
#include <math.h>
#include <stdint.h>

// ---------------- problem constants ----------------
#define B_    2
#define S_    2048
#define DIN   2048
#define DOUT  2048
#define NH    16
#define HD    128
#define LAT   256
#define ROWS  (B_ * S_)            // 4096
#define ATT_SCALE 0.08838834764831845f   // 1/sqrt(128)

// ---------------- scratch (device globals: allocation-free) ----------------
__device__ float g_q[ROWS * DOUT];
__device__ float g_lat[ROWS * LAT];
__device__ float g_k[ROWS * DOUT];
__device__ float g_v[ROWS * DOUT];
__device__ float g_ctx[ROWS * DOUT];

__device__ __forceinline__ uint32_t f2tf32(float x) {
    uint32_t r;
    asm("cvt.rna.tf32.f32 %0, %1;" : "=r"(r) : "f"(x));
    return r;
}

// split x into tf32 hi + tf32 lo (error-compensated tf32x3)
__device__ __forceinline__ void split32(float x, uint32_t& h, uint32_t& l) {
    asm("cvt.rna.tf32.f32 %0, %1;" : "=r"(h) : "f"(x));
    float r = x - __uint_as_float(h);
    asm("cvt.rna.tf32.f32 %0, %1;" : "=r"(l) : "f"(r));
}

__device__ __forceinline__ void mma_tf32(float* d, const uint32_t* a, const uint32_t* b) {
    asm volatile(
        "mma.sync.aligned.m16n8k8.row.col.f32.tf32.tf32.f32 "
        "{%0,%1,%2,%3}, {%4,%5,%6,%7}, {%8,%9}, {%0,%1,%2,%3};"
        : "+f"(d[0]), "+f"(d[1]), "+f"(d[2]), "+f"(d[3])
        : "r"(a[0]), "r"(a[1]), "r"(a[2]), "r"(a[3]), "r"(b[0]), "r"(b[1]));
}

// ====================================================================
// TF32 tensor-core GEMM (unchanged)
// ====================================================================
#define AS_STRIDE 36
#define BS_STRIDE 136

__global__ __launch_bounds__(256) void tf32_gemm(
    const float* __restrict__ A, const float* __restrict__ Bm,
    float* __restrict__ C, const float* __restrict__ bias,
    int M, int N, int K)
{
    __shared__ uint32_t As[128 * AS_STRIDE];
    __shared__ uint32_t Bs[32 * BS_STRIDE];

    const int t    = threadIdx.x;
    const int lane = t & 31;
    const int warp = t >> 5;
    const int bm   = blockIdx.y * 128;
    const int bn   = blockIdx.x * 128;

    const int wm = (warp >> 1) * 32;
    const int wn = (warp & 1) * 64;
    const int g  = lane >> 2;
    const int tg = lane & 3;

    const int arow = t >> 3;
    const int acol = (t & 7) * 4;
    const int brow = t >> 5;
    const int bcol = (t & 31) * 4;

    const float* Ag = A  + (size_t)(bm + arow) * K + acol;
    const float* Bg = Bm + (size_t)brow * N + bn + bcol;

    float acc[2][8][4];
#pragma unroll
    for (int mt = 0; mt < 2; mt++)
#pragma unroll
        for (int nt = 0; nt < 8; nt++)
#pragma unroll
            for (int r = 0; r < 4; r++) acc[mt][nt][r] = 0.f;

    float4 pa[4], pb[4];

#define LDAB(k0)                                                            \
    {                                                                       \
        _Pragma("unroll")                                                   \
        for (int i = 0; i < 4; i++)                                         \
            pa[i] = *(const float4*)(Ag + (size_t)(i * 32) * K + (k0));     \
        _Pragma("unroll")                                                   \
        for (int i = 0; i < 4; i++)                                         \
            pb[i] = *(const float4*)(Bg + (size_t)((k0) + i * 8) * N);      \
    }

#define STAB()                                                              \
    {                                                                       \
        _Pragma("unroll")                                                   \
        for (int i = 0; i < 4; i++) {                                       \
            uint32_t* p = &As[(arow + 32 * i) * AS_STRIDE + acol];          \
            uint4 v;                                                        \
            v.x = f2tf32(pa[i].x); v.y = f2tf32(pa[i].y);                   \
            v.z = f2tf32(pa[i].z); v.w = f2tf32(pa[i].w);                   \
            *(uint4*)p = v;                                                 \
        }                                                                   \
        _Pragma("unroll")                                                   \
        for (int i = 0; i < 4; i++) {                                       \
            uint32_t* p = &Bs[(brow + 8 * i) * BS_STRIDE + bcol];           \
            uint4 v;                                                        \
            v.x = f2tf32(pb[i].x); v.y = f2tf32(pb[i].y);                   \
            v.z = f2tf32(pb[i].z); v.w = f2tf32(pb[i].w);                   \
            *(uint4*)p = v;                                                 \
        }                                                                   \
    }

    const int nkt = K >> 5;

    LDAB(0);
    STAB();
    __syncthreads();

    for (int kt = 0; kt < nkt; kt++) {
        if (kt + 1 < nkt) LDAB((kt + 1) * 32);

#pragma unroll
        for (int k8 = 0; k8 < 32; k8 += 8) {
            uint32_t af[2][4];
            uint32_t bf[8][2];
#pragma unroll
            for (int mt = 0; mt < 2; mt++) {
                int mb = wm + mt * 16;
                af[mt][0] = As[(mb + g) * AS_STRIDE + k8 + tg];
                af[mt][1] = As[(mb + g + 8) * AS_STRIDE + k8 + tg];
                af[mt][2] = As[(mb + g) * AS_STRIDE + k8 + tg + 4];
                af[mt][3] = As[(mb + g + 8) * AS_STRIDE + k8 + tg + 4];
            }
#pragma unroll
            for (int nt = 0; nt < 8; nt++) {
                int nb = wn + nt * 8 + g;
                bf[nt][0] = Bs[(k8 + tg) * BS_STRIDE + nb];
                bf[nt][1] = Bs[(k8 + tg + 4) * BS_STRIDE + nb];
            }
#pragma unroll
            for (int mt = 0; mt < 2; mt++)
#pragma unroll
                for (int nt = 0; nt < 8; nt++)
                    mma_tf32(acc[mt][nt], af[mt], bf[nt]);
        }
        __syncthreads();
        if (kt + 1 < nkt) {
            STAB();
            __syncthreads();
        }
    }

#pragma unroll
    for (int mt = 0; mt < 2; mt++) {
        int row0 = bm + wm + mt * 16 + g;
#pragma unroll
        for (int nt = 0; nt < 8; nt++) {
            int col = bn + wn + nt * 8 + tg * 2;
            float b0 = 0.f, b1 = 0.f;
            if (bias) { b0 = bias[col]; b1 = bias[col + 1]; }
            float2 v0, v1;
            v0.x = acc[mt][nt][0] + b0;
            v0.y = acc[mt][nt][1] + b1;
            v1.x = acc[mt][nt][2] + b0;
            v1.y = acc[mt][nt][3] + b1;
            *(float2*)(C + (size_t)row0 * N + col)       = v0;
            *(float2*)(C + (size_t)(row0 + 8) * N + col) = v1;
        }
    }
#undef LDAB
#undef STAB
}

// ====================================================================
// Tensor-core causal flash attention v2.
//  - Q pre-scaled by ATT_SCALE and pre-split {hi,lo} ONCE into smem
//  - QK^T in tf32x3 (exp-amplified errors stay tiny)
//  - PV in single tf32 (direct error, ~2e-4, acceptable)
//  - K/V global loads register-prefetched across compute
// Block = 256 threads (8 warps), Q tile 128 rows, K/V tile 32 rows.
// ====================================================================
#define FBM 128
#define FBN 32
#define Q2S 264   // u32 stride, {hi,lo} interleaved
#define K2S 264
#define VSS 136
#define PSS 40
#define FA_SMEM_BYTES ((128*Q2S + FBN*K2S + FBN*VSS + 128*PSS) * 4)

__global__ __launch_bounds__(256) void flash_attn_tc(
    const float* __restrict__ Qg, const float* __restrict__ Kg,
    const float* __restrict__ Vg, float* __restrict__ Ctx)
{
    extern __shared__ uint32_t smu[];
    uint32_t* Qs2 = smu;                     // [128][264]
    uint32_t* Ks2 = Qs2 + 128 * Q2S;         // [32][264]
    uint32_t* Vs  = Ks2 + FBN * K2S;         // [32][136] single tf32
    uint32_t* Ps  = Vs  + FBN * VSS;         // [128][40]  single tf32

    const int t    = threadIdx.x;
    const int lane = t & 31;
    const int warp = t >> 5;
    const int g    = lane >> 2;
    const int tg   = lane & 3;

    // longest blocks first
    const int qt = gridDim.x - 1 - blockIdx.x;
    const int qb = qt * FBM;
    const int bh = blockIdx.y;
    const int b  = bh >> 4;
    const int h  = bh & 15;

    const float* Qbase = Qg + (size_t)b * S_ * DOUT + (size_t)h * HD;
    const float* Kbase = Kg + (size_t)b * S_ * DOUT + (size_t)h * HD;
    const float* Vbase = Vg + (size_t)b * S_ * DOUT + (size_t)h * HD;

    // ---- load Q tile once: scale, split, store interleaved ----
    for (int i = t; i < FBM * (HD / 4); i += 256) {
        int r  = i >> 5;
        int c4 = (i & 31) * 4;
        float4 qv = *(const float4*)(Qbase + (size_t)(qb + r) * DOUT + c4);
        uint4 hv0, hv1;
        split32(qv.x * ATT_SCALE, hv0.x, hv0.y);
        split32(qv.y * ATT_SCALE, hv0.z, hv0.w);
        split32(qv.z * ATT_SCALE, hv1.x, hv1.y);
        split32(qv.w * ATT_SCALE, hv1.z, hv1.w);
        *(uint4*)&Qs2[r * Q2S + 2 * c4]     = hv0;
        *(uint4*)&Qs2[r * Q2S + 2 * c4 + 4] = hv1;
    }

    float oacc[16][4];
#pragma unroll
    for (int nt = 0; nt < 16; nt++)
#pragma unroll
        for (int r = 0; r < 4; r++) oacc[nt][r] = 0.f;

    float m0 = -INFINITY, m1 = -INFINITY, l0 = 0.f, l1 = 0.f;
    const int r0 = qb + warp * 16 + g;
    const int r1 = r0 + 8;
    const int qrow0 = (warp * 16 + g) * Q2S;
    const int qrow1 = qrow0 + 8 * Q2S;
    const int prow0 = (warp * 16 + g) * PSS;
    const int prow1 = prow0 + 8 * PSS;

    float4 pk[4], pv[4];

#define LDKV(kb_)                                                              \
    {                                                                          \
        _Pragma("unroll")                                                      \
        for (int i = 0; i < 4; i++) {                                          \
            int idx = t + 256 * i;                                             \
            int r   = idx >> 5;                                                \
            int c4  = (idx & 31) * 4;                                          \
            pk[i] = *(const float4*)(Kbase + (size_t)((kb_) + r) * DOUT + c4); \
            pv[i] = *(const float4*)(Vbase + (size_t)((kb_) + r) * DOUT + c4); \
        }                                                                      \
    }

#define STKV()                                                                 \
    {                                                                          \
        _Pragma("unroll")                                                      \
        for (int i = 0; i < 4; i++) {                                          \
            int idx = t + 256 * i;                                             \
            int r   = idx >> 5;                                                \
            int c4  = (idx & 31) * 4;                                          \
            uint4 h0, h1;                                                      \
            split32(pk[i].x, h0.x, h0.y); split32(pk[i].y, h0.z, h0.w);        \
            split32(pk[i].z, h1.x, h1.y); split32(pk[i].w, h1.z, h1.w);        \
            *(uint4*)&Ks2[r * K2S + 2 * c4]     = h0;                          \
            *(uint4*)&Ks2[r * K2S + 2 * c4 + 4] = h1;                          \
            uint4 vv;                                                          \
            vv.x = f2tf32(pv[i].x); vv.y = f2tf32(pv[i].y);                    \
            vv.z = f2tf32(pv[i].z); vv.w = f2tf32(pv[i].w);                    \
            *(uint4*)&Vs[r * VSS + c4] = vv;                                   \
        }                                                                      \
    }

    const int nkt = qb / FBN + 4;

    LDKV(0);
    STKV();
    __syncthreads();

    for (int kt = 0; kt < nkt; kt++) {
        const int kb = kt * FBN;
        if (kt + 1 < nkt) LDKV(kb + FBN);

        // ---- S = Q K^T (tf32x3), warp tile 16x32 ----
        float sacc[4][4];
#pragma unroll
        for (int nt = 0; nt < 4; nt++)
#pragma unroll
            for (int r = 0; r < 4; r++) sacc[nt][r] = 0.f;

#pragma unroll
        for (int k8 = 0; k8 < HD; k8 += 8) {
            uint32_t ah[4], al[4];
            {
                uint2 q0 = *(const uint2*)&Qs2[qrow0 + 2 * (k8 + tg)];
                uint2 q1 = *(const uint2*)&Qs2[qrow1 + 2 * (k8 + tg)];
                uint2 q2 = *(const uint2*)&Qs2[qrow0 + 2 * (k8 + tg + 4)];
                uint2 q3 = *(const uint2*)&Qs2[qrow1 + 2 * (k8 + tg + 4)];
                ah[0] = q0.x; al[0] = q0.y;
                ah[1] = q1.x; al[1] = q1.y;
                ah[2] = q2.x; al[2] = q2.y;
                ah[3] = q3.x; al[3] = q3.y;
            }
#pragma unroll
            for (int nt = 0; nt < 4; nt++) {
                uint2 b0 = *(const uint2*)&Ks2[(nt * 8 + g) * K2S + 2 * (k8 + tg)];
                uint2 b1 = *(const uint2*)&Ks2[(nt * 8 + g) * K2S + 2 * (k8 + tg + 4)];
                uint32_t bhi[2] = {b0.x, b1.x};
                uint32_t blo[2] = {b0.y, b1.y};
                mma_tf32(sacc[nt], ah, bhi);
                mma_tf32(sacc[nt], al, bhi);
                mma_tf32(sacc[nt], ah, blo);
            }
        }

        // ---- causal mask (Q pre-scaled; positions only) ----
        if (kb + FBN - 1 > qb) {
#pragma unroll
            for (int nt = 0; nt < 4; nt++) {
                int c0 = kb + nt * 8 + 2 * tg;
                int c1 = c0 + 1;
                if (c0 > r0) sacc[nt][0] = -INFINITY;
                if (c1 > r0) sacc[nt][1] = -INFINITY;
                if (c0 > r1) sacc[nt][2] = -INFINITY;
                if (c1 > r1) sacc[nt][3] = -INFINITY;
            }
        }

        // ---- online softmax ----
        float mx0 = -INFINITY, mx1 = -INFINITY;
#pragma unroll
        for (int nt = 0; nt < 4; nt++) {
            mx0 = fmaxf(mx0, fmaxf(sacc[nt][0], sacc[nt][1]));
            mx1 = fmaxf(mx1, fmaxf(sacc[nt][2], sacc[nt][3]));
        }
        mx0 = fmaxf(mx0, __shfl_xor_sync(0xffffffffu, mx0, 1));
        mx0 = fmaxf(mx0, __shfl_xor_sync(0xffffffffu, mx0, 2));
        mx1 = fmaxf(mx1, __shfl_xor_sync(0xffffffffu, mx1, 1));
        mx1 = fmaxf(mx1, __shfl_xor_sync(0xffffffffu, mx1, 2));

        float nm0 = fmaxf(m0, mx0), nm1 = fmaxf(m1, mx1);
        float f0 = __expf(m0 - nm0), f1 = __expf(m1 - nm1);
        m0 = nm0; m1 = nm1;

        float s0 = 0.f, s1 = 0.f;
#pragma unroll
        for (int nt = 0; nt < 4; nt++) {
            float p0 = __expf(sacc[nt][0] - nm0);
            float p1 = __expf(sacc[nt][1] - nm0);
            float p2 = __expf(sacc[nt][2] - nm1);
            float p3 = __expf(sacc[nt][3] - nm1);
            s0 += p0 + p1;
            s1 += p2 + p3;
            uint2 w0, w1;
            w0.x = f2tf32(p0); w0.y = f2tf32(p1);
            w1.x = f2tf32(p2); w1.y = f2tf32(p3);
            *(uint2*)&Ps[prow0 + nt * 8 + 2 * tg] = w0;
            *(uint2*)&Ps[prow1 + nt * 8 + 2 * tg] = w1;
        }
        s0 += __shfl_xor_sync(0xffffffffu, s0, 1);
        s0 += __shfl_xor_sync(0xffffffffu, s0, 2);
        s1 += __shfl_xor_sync(0xffffffffu, s1, 1);
        s1 += __shfl_xor_sync(0xffffffffu, s1, 2);
        l0 = l0 * f0 + s0;
        l1 = l1 * f1 + s1;

#pragma unroll
        for (int nt = 0; nt < 16; nt++) {
            oacc[nt][0] *= f0;
            oacc[nt][1] *= f0;
            oacc[nt][2] *= f1;
            oacc[nt][3] *= f1;
        }
        __syncwarp();   // Ps is warp-private: only warp sync needed

        // ---- O += P V (single tf32), warp tile 16x128, k = 32 ----
#pragma unroll
        for (int k8 = 0; k8 < FBN; k8 += 8) {
            uint32_t a[4];
            a[0] = Ps[prow0 + k8 + tg];
            a[1] = Ps[prow1 + k8 + tg];
            a[2] = Ps[prow0 + k8 + tg + 4];
            a[3] = Ps[prow1 + k8 + tg + 4];
#pragma unroll
            for (int nt = 0; nt < 16; nt++) {
                uint32_t bf[2];
                bf[0] = Vs[(k8 + tg) * VSS + nt * 8 + g];
                bf[1] = Vs[(k8 + tg + 4) * VSS + nt * 8 + g];
                mma_tf32(oacc[nt], a, bf);
            }
        }

        __syncthreads();           // everyone done reading Ks2/Vs
        if (kt + 1 < nkt) {
            STKV();
            __syncthreads();
        }
    }

    // ---- epilogue ----
    float inv0 = 1.f / l0, inv1 = 1.f / l1;
    float* out0 = Ctx + ((size_t)b * S_ + r0) * DOUT + (size_t)h * HD;
    float* out1 = Ctx + ((size_t)b * S_ + r1) * DOUT + (size_t)h * HD;
#pragma unroll
    for (int nt = 0; nt < 16; nt++) {
        int c = nt * 8 + 2 * tg;
        *(float2*)(out0 + c) = make_float2(oacc[nt][0] * inv0, oacc[nt][1] * inv0);
        *(float2*)(out1 + c) = make_float2(oacc[nt][2] * inv1, oacc[nt][3] * inv1);
    }
#undef LDKV
#undef STKV
}

// ====================================================================
// launch
// ====================================================================
extern "C" void kernel_launch(void* const* d_in, const int* in_sizes, int n_in,
                              void* d_out, int out_size)
{
    const float* x    = (const float*)d_in[0];
    const float* Wq   = (const float*)d_in[1];
    const float* Wdkv = (const float*)d_in[2];
    const float* Wuk  = (const float*)d_in[3];
    const float* Wuv  = (const float*)d_in[4];
    const float* Wout = (const float*)d_in[5];
    const float* bout = (const float*)d_in[6];
    float* out = (float*)d_out;

    float *q, *lat, *k, *v, *ctx;
    cudaGetSymbolAddress((void**)&q,   g_q);
    cudaGetSymbolAddress((void**)&lat, g_lat);
    cudaGetSymbolAddress((void**)&k,   g_k);
    cudaGetSymbolAddress((void**)&v,   g_v);
    cudaGetSymbolAddress((void**)&ctx, g_ctx);

    cudaFuncSetAttribute(flash_attn_tc,
                         cudaFuncAttributeMaxDynamicSharedMemorySize,
                         FA_SMEM_BYTES);

    tf32_gemm<<<dim3(DOUT / 128, ROWS / 128), 256>>>(x, Wq, q, nullptr, ROWS, DOUT, DIN);
    tf32_gemm<<<dim3(LAT / 128, ROWS / 128), 256>>>(x, Wdkv, lat, nullptr, ROWS, LAT, DIN);
    tf32_gemm<<<dim3(DOUT / 128, ROWS / 128), 256>>>(lat, Wuk, k, nullptr, ROWS, DOUT, LAT);
    tf32_gemm<<<dim3(DOUT / 128, ROWS / 128), 256>>>(lat, Wuv, v, nullptr, ROWS, DOUT, LAT);
    flash_attn_tc<<<dim3(S_ / FBM, B_ * NH), 256, FA_SMEM_BYTES>>>(q, k, v, ctx);
    tf32_gemm<<<dim3(DOUT / 128, ROWS / 128), 256>>>(ctx, Wout, out, bout, ROWS, DOUT, DOUT);
}

// round 5
// speedup vs baseline: 2.8556x; 1.1261x over previous
#include <cuda_runtime.h>
#include <cuda_fp16.h>
#include <math.h>
#include <stdint.h>

// ---------------- problem constants ----------------
#define B_    2
#define S_    2048
#define DIN   2048
#define DOUT  2048
#define NH    16
#define HD    128
#define LAT   256
#define ROWS  (B_ * S_)            // 4096
#define ATT_SCALE 0.08838834764831845f   // 1/sqrt(128)

// ---------------- scratch ----------------
__device__ float g_q[ROWS * DOUT];
__device__ float g_lat[ROWS * LAT];
__device__ float g_k[ROWS * DOUT];
__device__ float g_v[ROWS * DOUT];
__device__ float g_ctx[ROWS * DOUT];

__device__ __forceinline__ uint32_t f2tf32(float x) {
    uint32_t r;
    asm("cvt.rna.tf32.f32 %0, %1;" : "=r"(r) : "f"(x));
    return r;
}

__device__ __forceinline__ void mma_tf32(float* d, const uint32_t* a, const uint32_t* b) {
    asm volatile(
        "mma.sync.aligned.m16n8k8.row.col.f32.tf32.tf32.f32 "
        "{%0,%1,%2,%3}, {%4,%5,%6,%7}, {%8,%9}, {%0,%1,%2,%3};"
        : "+f"(d[0]), "+f"(d[1]), "+f"(d[2]), "+f"(d[3])
        : "r"(a[0]), "r"(a[1]), "r"(a[2]), "r"(a[3]), "r"(b[0]), "r"(b[1]));
}

__device__ __forceinline__ void mma_f16(float* d, const uint32_t* a, const uint32_t* b) {
    asm volatile(
        "mma.sync.aligned.m16n8k16.row.col.f32.f16.f16.f32 "
        "{%0,%1,%2,%3}, {%4,%5,%6,%7}, {%8,%9}, {%0,%1,%2,%3};"
        : "+f"(d[0]), "+f"(d[1]), "+f"(d[2]), "+f"(d[3])
        : "r"(a[0]), "r"(a[1]), "r"(a[2]), "r"(a[3]), "r"(b[0]), "r"(b[1]));
}

// packed-pair slot: pair p (= k/2) -> u32 index within row so that the
// LDS.64 at (kk*8 + 2*tg) yields (pair tg, pair tg+4) = mma b0/b1 (or a0/a2).
__device__ __forceinline__ int ppos(int p) {
    int pp = p & 7;
    int slot = (pp < 4) ? (2 * pp) : (2 * (pp - 4) + 1);
    return ((p >> 3) << 3) + slot;
}

__device__ __forceinline__ uint32_t h2pack(float lo, float hi) {
    __half2 h = __halves2half2(__float2half_rn(lo), __float2half_rn(hi));
    return *reinterpret_cast<uint32_t*>(&h);
}

// split (x,y) into fp16 hi-pair and fp16 lo-pair
__device__ __forceinline__ void splitpack(float x, float y, uint32_t& ph, uint32_t& pl) {
    __half hx = __float2half_rn(x), hy = __float2half_rn(y);
    __half lx = __float2half_rn(x - __half2float(hx));
    __half ly = __float2half_rn(y - __half2float(hy));
    __half2 a = __halves2half2(hx, hy);
    __half2 c = __halves2half2(lx, ly);
    ph = *reinterpret_cast<uint32_t*>(&a);
    pl = *reinterpret_cast<uint32_t*>(&c);
}

// ====================================================================
// TF32 tensor-core GEMM (unchanged)
// ====================================================================
#define AS_STRIDE 36
#define BS_STRIDE 136

__global__ __launch_bounds__(256) void tf32_gemm(
    const float* __restrict__ A, const float* __restrict__ Bm,
    float* __restrict__ C, const float* __restrict__ bias,
    int M, int N, int K)
{
    __shared__ uint32_t As[128 * AS_STRIDE];
    __shared__ uint32_t Bs[32 * BS_STRIDE];

    const int t    = threadIdx.x;
    const int lane = t & 31;
    const int warp = t >> 5;
    const int bm   = blockIdx.y * 128;
    const int bn   = blockIdx.x * 128;

    const int wm = (warp >> 1) * 32;
    const int wn = (warp & 1) * 64;
    const int g  = lane >> 2;
    const int tg = lane & 3;

    const int arow = t >> 3;
    const int acol = (t & 7) * 4;
    const int brow = t >> 5;
    const int bcol = (t & 31) * 4;

    const float* Ag = A  + (size_t)(bm + arow) * K + acol;
    const float* Bg = Bm + (size_t)brow * N + bn + bcol;

    float acc[2][8][4];
#pragma unroll
    for (int mt = 0; mt < 2; mt++)
#pragma unroll
        for (int nt = 0; nt < 8; nt++)
#pragma unroll
            for (int r = 0; r < 4; r++) acc[mt][nt][r] = 0.f;

    float4 pa[4], pb[4];

#define LDAB(k0)                                                            \
    {                                                                       \
        _Pragma("unroll")                                                   \
        for (int i = 0; i < 4; i++)                                         \
            pa[i] = *(const float4*)(Ag + (size_t)(i * 32) * K + (k0));     \
        _Pragma("unroll")                                                   \
        for (int i = 0; i < 4; i++)                                         \
            pb[i] = *(const float4*)(Bg + (size_t)((k0) + i * 8) * N);      \
    }

#define STAB()                                                              \
    {                                                                       \
        _Pragma("unroll")                                                   \
        for (int i = 0; i < 4; i++) {                                       \
            uint32_t* p = &As[(arow + 32 * i) * AS_STRIDE + acol];          \
            uint4 v;                                                        \
            v.x = f2tf32(pa[i].x); v.y = f2tf32(pa[i].y);                   \
            v.z = f2tf32(pa[i].z); v.w = f2tf32(pa[i].w);                   \
            *(uint4*)p = v;                                                 \
        }                                                                   \
        _Pragma("unroll")                                                   \
        for (int i = 0; i < 4; i++) {                                       \
            uint32_t* p = &Bs[(brow + 8 * i) * BS_STRIDE + bcol];           \
            uint4 v;                                                        \
            v.x = f2tf32(pb[i].x); v.y = f2tf32(pb[i].y);                   \
            v.z = f2tf32(pb[i].z); v.w = f2tf32(pb[i].w);                   \
            *(uint4*)p = v;                                                 \
        }                                                                   \
    }

    const int nkt = K >> 5;

    LDAB(0);
    STAB();
    __syncthreads();

    for (int kt = 0; kt < nkt; kt++) {
        if (kt + 1 < nkt) LDAB((kt + 1) * 32);

#pragma unroll
        for (int k8 = 0; k8 < 32; k8 += 8) {
            uint32_t af[2][4];
            uint32_t bf[8][2];
#pragma unroll
            for (int mt = 0; mt < 2; mt++) {
                int mb = wm + mt * 16;
                af[mt][0] = As[(mb + g) * AS_STRIDE + k8 + tg];
                af[mt][1] = As[(mb + g + 8) * AS_STRIDE + k8 + tg];
                af[mt][2] = As[(mb + g) * AS_STRIDE + k8 + tg + 4];
                af[mt][3] = As[(mb + g + 8) * AS_STRIDE + k8 + tg + 4];
            }
#pragma unroll
            for (int nt = 0; nt < 8; nt++) {
                int nb = wn + nt * 8 + g;
                bf[nt][0] = Bs[(k8 + tg) * BS_STRIDE + nb];
                bf[nt][1] = Bs[(k8 + tg + 4) * BS_STRIDE + nb];
            }
#pragma unroll
            for (int mt = 0; mt < 2; mt++)
#pragma unroll
                for (int nt = 0; nt < 8; nt++)
                    mma_tf32(acc[mt][nt], af[mt], bf[nt]);
        }
        __syncthreads();
        if (kt + 1 < nkt) {
            STAB();
            __syncthreads();
        }
    }

#pragma unroll
    for (int mt = 0; mt < 2; mt++) {
        int row0 = bm + wm + mt * 16 + g;
#pragma unroll
        for (int nt = 0; nt < 8; nt++) {
            int col = bn + wn + nt * 8 + tg * 2;
            float b0 = 0.f, b1 = 0.f;
            if (bias) { b0 = bias[col]; b1 = bias[col + 1]; }
            float2 v0, v1;
            v0.x = acc[mt][nt][0] + b0;
            v0.y = acc[mt][nt][1] + b1;
            v1.x = acc[mt][nt][2] + b0;
            v1.y = acc[mt][nt][3] + b1;
            *(float2*)(C + (size_t)row0 * N + col)       = v0;
            *(float2*)(C + (size_t)(row0 + 8) * N + col) = v1;
        }
    }
#undef LDAB
#undef STAB
}

// ====================================================================
// fp16 tensor-core causal flash attention.
// 512 threads / 16 warps, Q tile 128 rows, K/V tile 32 (double-buffered).
// QK^T: fp16x3 error-compensated (hh + cross accumulator chains).
// PV:   fp16 single-pass.
// Warp grid: wr = warp>>1 (rows 16wr..16wr+16), wc = warp&1 (col half).
// ====================================================================
#define FBM 128
#define FBN 32
#define QS 72     // u32 stride (64 data + 8 pad, stride%32==8 -> conflict-free)
#define KS 72
#define VS 40
#define SSD 40    // f32 stride for scores
#define PS 20
#define FA_U32 (2*128*QS + 2*2*32*KS + 2*128*VS + 128*SSD + 128*PS + 3*128)
#define FA_SMEM_BYTES (FA_U32 * 4)

__global__ __launch_bounds__(512) void flash_attn_f16(
    const float* __restrict__ Qg, const float* __restrict__ Kg,
    const float* __restrict__ Vg, float* __restrict__ Ctx)
{
    extern __shared__ uint32_t smu[];
    uint32_t* Qh = smu;                       // [128][72]
    uint32_t* Ql = Qh + 128 * QS;             // [128][72]
    uint32_t* Kh = Ql + 128 * QS;             // [2][32][72]
    uint32_t* Kl = Kh + 2 * 32 * KS;          // [2][32][72]
    uint32_t* Vp = Kl + 2 * 32 * KS;          // [2][128][40] (col-major packed pairs)
    float*    Ss = (float*)(Vp + 2 * 128 * VS);   // [128][40]
    uint32_t* Pp = (uint32_t*)(Ss + 128 * SSD);   // [128][20]
    float* sm_m = (float*)(Pp + 128 * PS);
    float* sm_l = sm_m + 128;
    float* sm_f = sm_l + 128;

    const int t    = threadIdx.x;
    const int lane = t & 31;
    const int warp = t >> 5;
    const int g    = lane >> 2;
    const int tg   = lane & 3;
    const int wr   = warp >> 1;
    const int wc   = warp & 1;

    // longest blocks first
    const int qt = gridDim.x - 1 - blockIdx.x;
    const int qb = qt * FBM;
    const int bh = blockIdx.y;
    const int b  = bh >> 4;
    const int h  = bh & 15;

    const float* Qbase = Qg + (size_t)b * S_ * DOUT + (size_t)h * HD;
    const float* Kbase = Kg + (size_t)b * S_ * DOUT + (size_t)h * HD;
    const float* Vbase = Vg + (size_t)b * S_ * DOUT + (size_t)h * HD;

    // ---- load Q once: scale, split hi/lo, packed-pair layout ----
    {
        int row = t >> 2;
        int c0  = (t & 3) * 4;
        const float* qrow = Qbase + (size_t)(qb + row) * DOUT;
#pragma unroll
        for (int j = 0; j < 8; j++) {
            int c4 = c0 + 16 * j;
            float4 q = *(const float4*)(qrow + c4);
            q.x *= ATT_SCALE; q.y *= ATT_SCALE;
            q.z *= ATT_SCALE; q.w *= ATT_SCALE;
            int p0 = c4 >> 1;
            int j0 = ppos(p0), j1 = ppos(p0 + 1);
            uint32_t ph, pl;
            splitpack(q.x, q.y, ph, pl);
            Qh[row * QS + j0] = ph; Ql[row * QS + j0] = pl;
            splitpack(q.z, q.w, ph, pl);
            Qh[row * QS + j1] = ph; Ql[row * QS + j1] = pl;
        }
    }
    if (t < 128) { sm_m[t] = -INFINITY; sm_l[t] = 0.f; }

    float oacc[8][4];
#pragma unroll
    for (int nt = 0; nt < 8; nt++)
#pragma unroll
        for (int r = 0; r < 4; r++) oacc[nt][r] = 0.f;

    const int r0  = 16 * wr + g;    // local Q row (this lane's fragment rows: r0, r0+8)
    const int gr0 = qb + r0;

    // loader mappings
    const int krow = t >> 4, kseg = t & 15;   // K: 32 rows x 2 float4 segs
    const int vrp  = t & 15, vcg  = t >> 4;   // V: 16 row-pairs x 32 col-groups
    float4 pk0, pk1, pv0, pv1;

#define LDKV(kb_)                                                                    \
    {                                                                                \
        pk0 = *(const float4*)(Kbase + (size_t)((kb_) + krow) * DOUT + kseg * 4);    \
        pk1 = *(const float4*)(Kbase + (size_t)((kb_) + krow) * DOUT + kseg * 4 + 64); \
        pv0 = *(const float4*)(Vbase + (size_t)((kb_) + 2 * vrp) * DOUT + vcg * 4);  \
        pv1 = *(const float4*)(Vbase + (size_t)((kb_) + 2 * vrp + 1) * DOUT + vcg * 4); \
    }

#define STKV(buf)                                                                    \
    {                                                                                \
        uint32_t* kh = Kh + (buf) * 32 * KS + krow * KS;                             \
        uint32_t* kl = Kl + (buf) * 32 * KS + krow * KS;                             \
        {                                                                            \
            int c4 = kseg * 4; int p0 = c4 >> 1;                                     \
            int j0 = ppos(p0), j1 = ppos(p0 + 1);                                    \
            uint32_t ph, pl;                                                         \
            splitpack(pk0.x, pk0.y, ph, pl); kh[j0] = ph; kl[j0] = pl;               \
            splitpack(pk0.z, pk0.w, ph, pl); kh[j1] = ph; kl[j1] = pl;               \
        }                                                                            \
        {                                                                            \
            int c4 = kseg * 4 + 64; int p0 = c4 >> 1;                                \
            int j0 = ppos(p0), j1 = ppos(p0 + 1);                                    \
            uint32_t ph, pl;                                                         \
            splitpack(pk1.x, pk1.y, ph, pl); kh[j0] = ph; kl[j0] = pl;               \
            splitpack(pk1.z, pk1.w, ph, pl); kh[j1] = ph; kl[j1] = pl;               \
        }                                                                            \
        {                                                                            \
            uint32_t* vp = Vp + (buf) * 128 * VS;                                    \
            int jv = ppos(vrp);                                                      \
            vp[(vcg * 4 + 0) * VS + jv] = h2pack(pv0.x, pv1.x);                      \
            vp[(vcg * 4 + 1) * VS + jv] = h2pack(pv0.y, pv1.y);                      \
            vp[(vcg * 4 + 2) * VS + jv] = h2pack(pv0.z, pv1.z);                      \
            vp[(vcg * 4 + 3) * VS + jv] = h2pack(pv0.w, pv1.w);                      \
        }                                                                            \
    }

    const int nkt = qb / FBN + 4;

    LDKV(0);
    STKV(0);
    __syncthreads();

    for (int kt = 0; kt < nkt; kt++) {
        const int kb  = kt * FBN;
        const int cur = kt & 1;
        if (kt + 1 < nkt) LDKV(kb + FBN);

        const uint32_t* khb = Kh + cur * 32 * KS;
        const uint32_t* klb = Kl + cur * 32 * KS;

        // ---- S = Q K^T, fp16x3, split accumulator chains ----
        float shh[2][4], shx[2][4];
#pragma unroll
        for (int nt = 0; nt < 2; nt++)
#pragma unroll
            for (int r = 0; r < 4; r++) { shh[nt][r] = 0.f; shx[nt][r] = 0.f; }

#pragma unroll
        for (int kk = 0; kk < 8; kk++) {
            uint2 qh0 = *(const uint2*)&Qh[r0 * QS + kk * 8 + 2 * tg];
            uint2 qh1 = *(const uint2*)&Qh[(r0 + 8) * QS + kk * 8 + 2 * tg];
            uint2 ql0 = *(const uint2*)&Ql[r0 * QS + kk * 8 + 2 * tg];
            uint2 ql1 = *(const uint2*)&Ql[(r0 + 8) * QS + kk * 8 + 2 * tg];
            uint32_t ah[4] = {qh0.x, qh1.x, qh0.y, qh1.y};
            uint32_t al[4] = {ql0.x, ql1.x, ql0.y, ql1.y};
#pragma unroll
            for (int nt = 0; nt < 2; nt++) {
                int col = wc * 16 + nt * 8 + g;
                uint2 kh2 = *(const uint2*)&khb[col * KS + kk * 8 + 2 * tg];
                uint2 kl2 = *(const uint2*)&klb[col * KS + kk * 8 + 2 * tg];
                uint32_t bhv[2] = {kh2.x, kh2.y};
                uint32_t blv[2] = {kl2.x, kl2.y};
                mma_f16(shh[nt], ah, bhv);
                mma_f16(shx[nt], al, bhv);
                mma_f16(shx[nt], ah, blv);
            }
        }

        // ---- combine, mask, write scores ----
#pragma unroll
        for (int nt = 0; nt < 2; nt++) {
            int cb = kb + wc * 16 + nt * 8 + 2 * tg;
            float s0 = shh[nt][0] + shx[nt][0];
            float s1 = shh[nt][1] + shx[nt][1];
            float s2 = shh[nt][2] + shx[nt][2];
            float s3 = shh[nt][3] + shx[nt][3];
            if (cb     > gr0)     s0 = -INFINITY;
            if (cb + 1 > gr0)     s1 = -INFINITY;
            if (cb     > gr0 + 8) s2 = -INFINITY;
            if (cb + 1 > gr0 + 8) s3 = -INFINITY;
            *(float2*)&Ss[r0 * SSD + wc * 16 + nt * 8 + 2 * tg]       = make_float2(s0, s1);
            *(float2*)&Ss[(r0 + 8) * SSD + wc * 16 + nt * 8 + 2 * tg] = make_float2(s2, s3);
        }
        __syncthreads();   // B1: scores visible to softmax owners

        // ---- softmax: 4 threads per row, 8 cols each ----
        {
            int row = t >> 2, q = t & 3;
            float sv[8];
#pragma unroll
            for (int j = 0; j < 8; j++) sv[j] = Ss[row * SSD + q * 8 + j];
            float m_old = sm_m[row];
            float rmax = sv[0];
#pragma unroll
            for (int j = 1; j < 8; j++) rmax = fmaxf(rmax, sv[j]);
            rmax = fmaxf(rmax, __shfl_xor_sync(0xffffffffu, rmax, 1));
            rmax = fmaxf(rmax, __shfl_xor_sync(0xffffffffu, rmax, 2));
            float nm = fmaxf(m_old, rmax);
            float f  = __expf(m_old - nm);
            float sum = 0.f;
#pragma unroll
            for (int j = 0; j < 8; j++) { sv[j] = __expf(sv[j] - nm); sum += sv[j]; }
            sum += __shfl_xor_sync(0xffffffffu, sum, 1);
            sum += __shfl_xor_sync(0xffffffffu, sum, 2);
            if (q == 0) {
                sm_m[row] = nm;
                sm_l[row] = sm_l[row] * f + sum;
                sm_f[row] = f;
            }
            // pack P (fp16) into packed-pair layout: pairs 4q..4q+3
#pragma unroll
            for (int i = 0; i < 4; i++)
                Pp[row * PS + (q >> 1) * 8 + 2 * i + (q & 1)] =
                    h2pack(sv[2 * i], sv[2 * i + 1]);
        }
        __syncthreads();   // B2: P + stats visible

        // ---- rescale O ----
        {
            float f0 = sm_f[r0], f1 = sm_f[r0 + 8];
#pragma unroll
            for (int nt = 0; nt < 8; nt++) {
                oacc[nt][0] *= f0; oacc[nt][1] *= f0;
                oacc[nt][2] *= f1; oacc[nt][3] *= f1;
            }
        }

        // ---- O += P V (fp16), warp tile 16 x 64 ----
        {
            const uint32_t* vpb = Vp + cur * 128 * VS;
#pragma unroll
            for (int kk = 0; kk < 2; kk++) {
                uint2 pw0 = *(const uint2*)&Pp[r0 * PS + kk * 8 + 2 * tg];
                uint2 pw1 = *(const uint2*)&Pp[(r0 + 8) * PS + kk * 8 + 2 * tg];
                uint32_t a[4] = {pw0.x, pw1.x, pw0.y, pw1.y};
#pragma unroll
                for (int nt = 0; nt < 8; nt++) {
                    int col = wc * 64 + nt * 8 + g;
                    uint2 bv = *(const uint2*)&vpb[col * VS + kk * 8 + 2 * tg];
                    uint32_t bb[2] = {bv.x, bv.y};
                    mma_f16(oacc[nt], a, bb);
                }
            }
        }

        if (kt + 1 < nkt) STKV((kt + 1) & 1);
        __syncthreads();   // B3: next K/V buffer ready; Ss/Pp reusable
    }

    // ---- epilogue ----
    float inv0 = 1.f / sm_l[r0], inv1 = 1.f / sm_l[r0 + 8];
    float* o0 = Ctx + ((size_t)b * S_ + gr0) * DOUT + (size_t)h * HD + wc * 64;
    float* o1 = o0 + (size_t)8 * DOUT;
#pragma unroll
    for (int nt = 0; nt < 8; nt++) {
        *(float2*)(o0 + nt * 8 + 2 * tg) =
            make_float2(oacc[nt][0] * inv0, oacc[nt][1] * inv0);
        *(float2*)(o1 + nt * 8 + 2 * tg) =
            make_float2(oacc[nt][2] * inv1, oacc[nt][3] * inv1);
    }
#undef LDKV
#undef STKV
}

// ====================================================================
// launch
// ====================================================================
extern "C" void kernel_launch(void* const* d_in, const int* in_sizes, int n_in,
                              void* d_out, int out_size)
{
    const float* x    = (const float*)d_in[0];
    const float* Wq   = (const float*)d_in[1];
    const float* Wdkv = (const float*)d_in[2];
    const float* Wuk  = (const float*)d_in[3];
    const float* Wuv  = (const float*)d_in[4];
    const float* Wout = (const float*)d_in[5];
    const float* bout = (const float*)d_in[6];
    float* out = (float*)d_out;

    float *q, *lat, *k, *v, *ctx;
    cudaGetSymbolAddress((void**)&q,   g_q);
    cudaGetSymbolAddress((void**)&lat, g_lat);
    cudaGetSymbolAddress((void**)&k,   g_k);
    cudaGetSymbolAddress((void**)&v,   g_v);
    cudaGetSymbolAddress((void**)&ctx, g_ctx);

    cudaFuncSetAttribute(flash_attn_f16,
                         cudaFuncAttributeMaxDynamicSharedMemorySize,
                         FA_SMEM_BYTES);

    tf32_gemm<<<dim3(DOUT / 128, ROWS / 128), 256>>>(x, Wq, q, nullptr, ROWS, DOUT, DIN);
    tf32_gemm<<<dim3(LAT / 128, ROWS / 128), 256>>>(x, Wdkv, lat, nullptr, ROWS, LAT, DIN);
    tf32_gemm<<<dim3(DOUT / 128, ROWS / 128), 256>>>(lat, Wuk, k, nullptr, ROWS, DOUT, LAT);
    tf32_gemm<<<dim3(DOUT / 128, ROWS / 128), 256>>>(lat, Wuv, v, nullptr, ROWS, DOUT, LAT);
    flash_attn_f16<<<dim3(S_ / FBM, B_ * NH), 512, FA_SMEM_BYTES>>>(q, k, v, ctx);
    tf32_gemm<<<dim3(DOUT / 128, ROWS / 128), 256>>>(ctx, Wout, out, bout, ROWS, DOUT, DOUT);
}

// round 6
// speedup vs baseline: 3.2676x; 1.1443x over previous
#include <cuda_runtime.h>
#include <cuda_fp16.h>
#include <math.h>
#include <stdint.h>

// ---------------- problem constants ----------------
#define B_    2
#define S_    2048
#define DIN   2048
#define DOUT  2048
#define NH    16
#define HD    128
#define LAT   256
#define ROWS  (B_ * S_)            // 4096
#define ATT_SCALE 0.08838834764831845f   // 1/sqrt(128)

// ---------------- scratch ----------------
__device__ float g_q[ROWS * DOUT];
__device__ float g_lat[ROWS * LAT];
__device__ float g_k[ROWS * DOUT];
__device__ float g_v[ROWS * DOUT];
__device__ float g_ctx[ROWS * DOUT];

__device__ __forceinline__ uint32_t f2tf32(float x) {
    uint32_t r;
    asm("cvt.rna.tf32.f32 %0, %1;" : "=r"(r) : "f"(x));
    return r;
}

__device__ __forceinline__ void mma_tf32(float* d, const uint32_t* a, const uint32_t* b) {
    asm volatile(
        "mma.sync.aligned.m16n8k8.row.col.f32.tf32.tf32.f32 "
        "{%0,%1,%2,%3}, {%4,%5,%6,%7}, {%8,%9}, {%0,%1,%2,%3};"
        : "+f"(d[0]), "+f"(d[1]), "+f"(d[2]), "+f"(d[3])
        : "r"(a[0]), "r"(a[1]), "r"(a[2]), "r"(a[3]), "r"(b[0]), "r"(b[1]));
}

__device__ __forceinline__ void mma_f16(float* d, const uint32_t* a, const uint32_t* b) {
    asm volatile(
        "mma.sync.aligned.m16n8k16.row.col.f32.f16.f16.f32 "
        "{%0,%1,%2,%3}, {%4,%5,%6,%7}, {%8,%9}, {%0,%1,%2,%3};"
        : "+f"(d[0]), "+f"(d[1]), "+f"(d[2]), "+f"(d[3])
        : "r"(a[0]), "r"(a[1]), "r"(a[2]), "r"(a[3]), "r"(b[0]), "r"(b[1]));
}

// packed-pair slot: pair p -> u32 index so LDS.64 at (kk*8 + 2*tg) yields
// (pair tg, pair tg+4) = mma b0/b1.
__device__ __forceinline__ int ppos(int p) {
    int pp = p & 7;
    int slot = (pp < 4) ? (2 * pp) : (2 * (pp - 4) + 1);
    return ((p >> 3) << 3) + slot;
}

__device__ __forceinline__ uint32_t h2pack(float lo, float hi) {
    __half2 h = __halves2half2(__float2half_rn(lo), __float2half_rn(hi));
    return *reinterpret_cast<uint32_t*>(&h);
}

// split (x,y) into fp16 hi-pair and fp16 lo-pair
__device__ __forceinline__ void splitpack(float x, float y, uint32_t& ph, uint32_t& pl) {
    __half hx = __float2half_rn(x), hy = __float2half_rn(y);
    __half lx = __float2half_rn(x - __half2float(hx));
    __half ly = __float2half_rn(y - __half2float(hy));
    __half2 a = __halves2half2(hx, hy);
    __half2 c = __halves2half2(lx, ly);
    ph = *reinterpret_cast<uint32_t*>(&a);
    pl = *reinterpret_cast<uint32_t*>(&c);
}

// ====================================================================
// TF32 tensor-core GEMM (unchanged)
// ====================================================================
#define AS_STRIDE 36
#define BS_STRIDE 136

__global__ __launch_bounds__(256) void tf32_gemm(
    const float* __restrict__ A, const float* __restrict__ Bm,
    float* __restrict__ C, const float* __restrict__ bias,
    int M, int N, int K)
{
    __shared__ uint32_t As[128 * AS_STRIDE];
    __shared__ uint32_t Bs[32 * BS_STRIDE];

    const int t    = threadIdx.x;
    const int lane = t & 31;
    const int warp = t >> 5;
    const int bm   = blockIdx.y * 128;
    const int bn   = blockIdx.x * 128;

    const int wm = (warp >> 1) * 32;
    const int wn = (warp & 1) * 64;
    const int g  = lane >> 2;
    const int tg = lane & 3;

    const int arow = t >> 3;
    const int acol = (t & 7) * 4;
    const int brow = t >> 5;
    const int bcol = (t & 31) * 4;

    const float* Ag = A  + (size_t)(bm + arow) * K + acol;
    const float* Bg = Bm + (size_t)brow * N + bn + bcol;

    float acc[2][8][4];
#pragma unroll
    for (int mt = 0; mt < 2; mt++)
#pragma unroll
        for (int nt = 0; nt < 8; nt++)
#pragma unroll
            for (int r = 0; r < 4; r++) acc[mt][nt][r] = 0.f;

    float4 pa[4], pb[4];

#define LDAB(k0)                                                            \
    {                                                                       \
        _Pragma("unroll")                                                   \
        for (int i = 0; i < 4; i++)                                         \
            pa[i] = *(const float4*)(Ag + (size_t)(i * 32) * K + (k0));     \
        _Pragma("unroll")                                                   \
        for (int i = 0; i < 4; i++)                                         \
            pb[i] = *(const float4*)(Bg + (size_t)((k0) + i * 8) * N);      \
    }

#define STAB()                                                              \
    {                                                                       \
        _Pragma("unroll")                                                   \
        for (int i = 0; i < 4; i++) {                                       \
            uint32_t* p = &As[(arow + 32 * i) * AS_STRIDE + acol];          \
            uint4 v;                                                        \
            v.x = f2tf32(pa[i].x); v.y = f2tf32(pa[i].y);                   \
            v.z = f2tf32(pa[i].z); v.w = f2tf32(pa[i].w);                   \
            *(uint4*)p = v;                                                 \
        }                                                                   \
        _Pragma("unroll")                                                   \
        for (int i = 0; i < 4; i++) {                                       \
            uint32_t* p = &Bs[(brow + 8 * i) * BS_STRIDE + bcol];           \
            uint4 v;                                                        \
            v.x = f2tf32(pb[i].x); v.y = f2tf32(pb[i].y);                   \
            v.z = f2tf32(pb[i].z); v.w = f2tf32(pb[i].w);                   \
            *(uint4*)p = v;                                                 \
        }                                                                   \
    }

    const int nkt = K >> 5;

    LDAB(0);
    STAB();
    __syncthreads();

    for (int kt = 0; kt < nkt; kt++) {
        if (kt + 1 < nkt) LDAB((kt + 1) * 32);

#pragma unroll
        for (int k8 = 0; k8 < 32; k8 += 8) {
            uint32_t af[2][4];
            uint32_t bf[8][2];
#pragma unroll
            for (int mt = 0; mt < 2; mt++) {
                int mb = wm + mt * 16;
                af[mt][0] = As[(mb + g) * AS_STRIDE + k8 + tg];
                af[mt][1] = As[(mb + g + 8) * AS_STRIDE + k8 + tg];
                af[mt][2] = As[(mb + g) * AS_STRIDE + k8 + tg + 4];
                af[mt][3] = As[(mb + g + 8) * AS_STRIDE + k8 + tg + 4];
            }
#pragma unroll
            for (int nt = 0; nt < 8; nt++) {
                int nb = wn + nt * 8 + g;
                bf[nt][0] = Bs[(k8 + tg) * BS_STRIDE + nb];
                bf[nt][1] = Bs[(k8 + tg + 4) * BS_STRIDE + nb];
            }
#pragma unroll
            for (int mt = 0; mt < 2; mt++)
#pragma unroll
                for (int nt = 0; nt < 8; nt++)
                    mma_tf32(acc[mt][nt], af[mt], bf[nt]);
        }
        __syncthreads();
        if (kt + 1 < nkt) {
            STAB();
            __syncthreads();
        }
    }

#pragma unroll
    for (int mt = 0; mt < 2; mt++) {
        int row0 = bm + wm + mt * 16 + g;
#pragma unroll
        for (int nt = 0; nt < 8; nt++) {
            int col = bn + wn + nt * 8 + tg * 2;
            float b0 = 0.f, b1 = 0.f;
            if (bias) { b0 = bias[col]; b1 = bias[col + 1]; }
            float2 v0, v1;
            v0.x = acc[mt][nt][0] + b0;
            v0.y = acc[mt][nt][1] + b1;
            v1.x = acc[mt][nt][2] + b0;
            v1.y = acc[mt][nt][3] + b1;
            *(float2*)(C + (size_t)row0 * N + col)       = v0;
            *(float2*)(C + (size_t)(row0 + 8) * N + col) = v1;
        }
    }
#undef LDAB
#undef STAB
}

// ====================================================================
// fp16 register-resident causal flash attention (FA-2 style).
// 256 threads / 8 warps. Q tile 128 rows; warp w owns rows 16w..16w+15.
// Q pre-scaled, pre-split fp16 hi/lo, held in REGISTERS as A-fragments.
// QK^T: fp16x3; softmax in registers (shuffles); P stays in registers
// (S C-fragment == PV A-fragment layout). PV: fp16 single.
// K/V tile 32 rows, double-buffered, ONE __syncthreads per tile.
// ====================================================================
#define FBM 128
#define FBN 32
#define KS 72     // u32 stride: 64 pair-slots + 8 pad (stride%32==8)
#define VS 40     // u32 stride: 16 pair-slots + pad (stride%32==8)
#define FA_U32 (2*32*KS*2 + 2*128*VS)
#define FA_SMEM_BYTES (FA_U32 * 4)

__global__ __launch_bounds__(256) void flash_attn_reg(
    const float* __restrict__ Qg, const float* __restrict__ Kg,
    const float* __restrict__ Vg, float* __restrict__ Ctx)
{
    extern __shared__ uint32_t smu[];
    uint32_t* Kh = smu;                  // [2][32][KS]
    uint32_t* Kl = Kh + 2 * 32 * KS;     // [2][32][KS]
    uint32_t* Vt = Kl + 2 * 32 * KS;     // [2][128][VS] transposed packed pairs

    const int t    = threadIdx.x;
    const int lane = t & 31;
    const int warp = t >> 5;
    const int g    = lane >> 2;
    const int tg   = lane & 3;

    // longest blocks first
    const int qt = gridDim.x - 1 - blockIdx.x;
    const int qb = qt * FBM;
    const int bh = blockIdx.y;
    const int b  = bh >> 4;
    const int h  = bh & 15;

    const float* Kbase = Kg + (size_t)b * S_ * DOUT + (size_t)h * HD;
    const float* Vbase = Vg + (size_t)b * S_ * DOUT + (size_t)h * HD;

    const int gr0  = qb + warp * 16 + g;     // this lane's fragment rows: gr0, gr0+8
    const int wmax = qb + warp * 16 + 15;    // warp's max row

    // ---- Q into register A-fragments (scaled, split hi/lo) ----
    uint32_t qh[8][4], ql[8][4];
    {
        const float* q0 = Qg + ((size_t)b * S_ + gr0) * DOUT + (size_t)h * HD;
        const float* q1 = q0 + (size_t)8 * DOUT;
#pragma unroll
        for (int kk = 0; kk < 8; kk++) {
            int c = 16 * kk + 2 * tg;
            float2 a0 = *(const float2*)(q0 + c);
            float2 a1 = *(const float2*)(q1 + c);
            float2 a2 = *(const float2*)(q0 + c + 8);
            float2 a3 = *(const float2*)(q1 + c + 8);
            splitpack(a0.x * ATT_SCALE, a0.y * ATT_SCALE, qh[kk][0], ql[kk][0]);
            splitpack(a1.x * ATT_SCALE, a1.y * ATT_SCALE, qh[kk][1], ql[kk][1]);
            splitpack(a2.x * ATT_SCALE, a2.y * ATT_SCALE, qh[kk][2], ql[kk][2]);
            splitpack(a3.x * ATT_SCALE, a3.y * ATT_SCALE, qh[kk][3], ql[kk][3]);
        }
    }

    float oacc[16][4];
#pragma unroll
    for (int nt = 0; nt < 16; nt++)
#pragma unroll
        for (int r = 0; r < 4; r++) oacc[nt][r] = 0.f;
    float m0 = -INFINITY, m1 = -INFINITY, l0 = 0.f, l1 = 0.f;

    // loader mappings (256 threads)
    const int vrp  = t & 15;          // V row-pair 0..15
    const int vcg  = (t >> 4) * 2;    // V col-group base (0,2,..,30)
    float4 pk[4], pv[4];

#define LDKV(kb_)                                                                     \
    {                                                                                 \
        _Pragma("unroll")                                                             \
        for (int i = 0; i < 4; i++) {                                                 \
            int idx = t + 256 * i;                                                    \
            int r   = idx >> 5;                                                       \
            int c4  = (idx & 31) * 4;                                                 \
            pk[i] = *(const float4*)(Kbase + (size_t)((kb_) + r) * DOUT + c4);        \
        }                                                                             \
        pv[0] = *(const float4*)(Vbase + (size_t)((kb_) + 2 * vrp) * DOUT + vcg * 4); \
        pv[1] = *(const float4*)(Vbase + (size_t)((kb_) + 2 * vrp + 1) * DOUT + vcg * 4); \
        pv[2] = *(const float4*)(Vbase + (size_t)((kb_) + 2 * vrp) * DOUT + (vcg + 1) * 4); \
        pv[3] = *(const float4*)(Vbase + (size_t)((kb_) + 2 * vrp + 1) * DOUT + (vcg + 1) * 4); \
    }

#define STKV(buf)                                                                     \
    {                                                                                 \
        _Pragma("unroll")                                                             \
        for (int i = 0; i < 4; i++) {                                                 \
            int idx = t + 256 * i;                                                    \
            int r   = idx >> 5;                                                       \
            int c4  = (idx & 31) * 4;                                                 \
            int p0  = c4 >> 1;                                                        \
            uint32_t* kh = Kh + (buf) * 32 * KS + r * KS;                             \
            uint32_t* kl = Kl + (buf) * 32 * KS + r * KS;                             \
            int j0 = ppos(p0), j1 = ppos(p0 + 1);                                     \
            uint32_t ph, pl;                                                          \
            splitpack(pk[i].x, pk[i].y, ph, pl); kh[j0] = ph; kl[j0] = pl;            \
            splitpack(pk[i].z, pk[i].w, ph, pl); kh[j1] = ph; kl[j1] = pl;            \
        }                                                                             \
        {                                                                             \
            uint32_t* vp = Vt + (buf) * 128 * VS;                                     \
            int jv = ppos(vrp);                                                       \
            vp[(vcg * 4 + 0) * VS + jv] = h2pack(pv[0].x, pv[1].x);                   \
            vp[(vcg * 4 + 1) * VS + jv] = h2pack(pv[0].y, pv[1].y);                   \
            vp[(vcg * 4 + 2) * VS + jv] = h2pack(pv[0].z, pv[1].z);                   \
            vp[(vcg * 4 + 3) * VS + jv] = h2pack(pv[0].w, pv[1].w);                   \
            vp[((vcg + 1) * 4 + 0) * VS + jv] = h2pack(pv[2].x, pv[3].x);             \
            vp[((vcg + 1) * 4 + 1) * VS + jv] = h2pack(pv[2].y, pv[3].y);             \
            vp[((vcg + 1) * 4 + 2) * VS + jv] = h2pack(pv[2].z, pv[3].z);             \
            vp[((vcg + 1) * 4 + 3) * VS + jv] = h2pack(pv[2].w, pv[3].w);             \
        }                                                                             \
    }

    const int nkt = qb / FBN + 4;

    LDKV(0);
    STKV(0);
    __syncthreads();

    for (int kt = 0; kt < nkt; kt++) {
        const int kb  = kt * FBN;
        const int cur = kt & 1;
        if (kt + 1 < nkt) LDKV(kb + FBN);

        if (kb <= wmax) {   // warp has at least one unmasked column here
            const uint32_t* khb = Kh + cur * 32 * KS;
            const uint32_t* klb = Kl + cur * 32 * KS;

            // ---- S = Q K^T, fp16x3, split accumulator chains ----
            float shh[4][4], shx[4][4];
#pragma unroll
            for (int nt = 0; nt < 4; nt++)
#pragma unroll
                for (int r = 0; r < 4; r++) { shh[nt][r] = 0.f; shx[nt][r] = 0.f; }

#pragma unroll
            for (int kk = 0; kk < 8; kk++) {
#pragma unroll
                for (int nt = 0; nt < 4; nt++) {
                    int row = (nt * 8 + g) * KS + kk * 8 + 2 * tg;
                    uint2 bh2 = *(const uint2*)&khb[row];
                    uint2 bl2 = *(const uint2*)&klb[row];
                    uint32_t bhv[2] = {bh2.x, bh2.y};
                    uint32_t blv[2] = {bl2.x, bl2.y};
                    mma_f16(shh[nt], qh[kk], bhv);
                    mma_f16(shx[nt], ql[kk], bhv);
                    mma_f16(shx[nt], qh[kk], blv);
                }
            }

            // ---- combine + causal mask ----
            float s[4][4];
#pragma unroll
            for (int nt = 0; nt < 4; nt++) {
#pragma unroll
                for (int r = 0; r < 4; r++) s[nt][r] = shh[nt][r] + shx[nt][r];
                if (kb + FBN - 1 > qb + warp * 16) {
                    int cb = kb + nt * 8 + 2 * tg;
                    if (cb     > gr0)     s[nt][0] = -INFINITY;
                    if (cb + 1 > gr0)     s[nt][1] = -INFINITY;
                    if (cb     > gr0 + 8) s[nt][2] = -INFINITY;
                    if (cb + 1 > gr0 + 8) s[nt][3] = -INFINITY;
                }
            }

            // ---- online softmax in registers ----
            float mx0 = -INFINITY, mx1 = -INFINITY;
#pragma unroll
            for (int nt = 0; nt < 4; nt++) {
                mx0 = fmaxf(mx0, fmaxf(s[nt][0], s[nt][1]));
                mx1 = fmaxf(mx1, fmaxf(s[nt][2], s[nt][3]));
            }
            mx0 = fmaxf(mx0, __shfl_xor_sync(0xffffffffu, mx0, 1));
            mx0 = fmaxf(mx0, __shfl_xor_sync(0xffffffffu, mx0, 2));
            mx1 = fmaxf(mx1, __shfl_xor_sync(0xffffffffu, mx1, 1));
            mx1 = fmaxf(mx1, __shfl_xor_sync(0xffffffffu, mx1, 2));

            float nm0 = fmaxf(m0, mx0), nm1 = fmaxf(m1, mx1);
            float f0 = __expf(m0 - nm0), f1 = __expf(m1 - nm1);
            m0 = nm0; m1 = nm1;

            uint32_t pa[2][4];   // PV A-fragments (== S C-fragment relayout)
            float s0 = 0.f, s1 = 0.f;
#pragma unroll
            for (int nt = 0; nt < 4; nt++) {
                float p0 = __expf(s[nt][0] - nm0);
                float p1 = __expf(s[nt][1] - nm0);
                float p2 = __expf(s[nt][2] - nm1);
                float p3 = __expf(s[nt][3] - nm1);
                s0 += p0 + p1;
                s1 += p2 + p3;
                pa[nt >> 1][(nt & 1) * 2 + 0] = h2pack(p0, p1);
                pa[nt >> 1][(nt & 1) * 2 + 1] = h2pack(p2, p3);
            }
            s0 += __shfl_xor_sync(0xffffffffu, s0, 1);
            s0 += __shfl_xor_sync(0xffffffffu, s0, 2);
            s1 += __shfl_xor_sync(0xffffffffu, s1, 1);
            s1 += __shfl_xor_sync(0xffffffffu, s1, 2);
            l0 = l0 * f0 + s0;
            l1 = l1 * f1 + s1;

#pragma unroll
            for (int nt = 0; nt < 16; nt++) {
                oacc[nt][0] *= f0; oacc[nt][1] *= f0;
                oacc[nt][2] *= f1; oacc[nt][3] *= f1;
            }

            // ---- O += P V (fp16), 16 independent n-chains ----
            const uint32_t* vpb = Vt + cur * 128 * VS;
#pragma unroll
            for (int kk = 0; kk < 2; kk++) {
#pragma unroll
                for (int nt = 0; nt < 16; nt++) {
                    uint2 bv = *(const uint2*)&vpb[(nt * 8 + g) * VS + kk * 8 + 2 * tg];
                    uint32_t bb[2] = {bv.x, bv.y};
                    mma_f16(oacc[nt], pa[kk], bb);
                }
            }
        }

        if (kt + 1 < nkt) STKV(cur ^ 1);
        __syncthreads();
    }

    // ---- epilogue ----
    float inv0 = 1.f / l0, inv1 = 1.f / l1;
    float* o0 = Ctx + ((size_t)b * S_ + gr0) * DOUT + (size_t)h * HD;
    float* o1 = o0 + (size_t)8 * DOUT;
#pragma unroll
    for (int nt = 0; nt < 16; nt++) {
        int c = nt * 8 + 2 * tg;
        *(float2*)(o0 + c) = make_float2(oacc[nt][0] * inv0, oacc[nt][1] * inv0);
        *(float2*)(o1 + c) = make_float2(oacc[nt][2] * inv1, oacc[nt][3] * inv1);
    }
#undef LDKV
#undef STKV
}

// ====================================================================
// launch
// ====================================================================
extern "C" void kernel_launch(void* const* d_in, const int* in_sizes, int n_in,
                              void* d_out, int out_size)
{
    const float* x    = (const float*)d_in[0];
    const float* Wq   = (const float*)d_in[1];
    const float* Wdkv = (const float*)d_in[2];
    const float* Wuk  = (const float*)d_in[3];
    const float* Wuv  = (const float*)d_in[4];
    const float* Wout = (const float*)d_in[5];
    const float* bout = (const float*)d_in[6];
    float* out = (float*)d_out;

    float *q, *lat, *k, *v, *ctx;
    cudaGetSymbolAddress((void**)&q,   g_q);
    cudaGetSymbolAddress((void**)&lat, g_lat);
    cudaGetSymbolAddress((void**)&k,   g_k);
    cudaGetSymbolAddress((void**)&v,   g_v);
    cudaGetSymbolAddress((void**)&ctx, g_ctx);

    cudaFuncSetAttribute(flash_attn_reg,
                         cudaFuncAttributeMaxDynamicSharedMemorySize,
                         FA_SMEM_BYTES);

    tf32_gemm<<<dim3(DOUT / 128, ROWS / 128), 256>>>(x, Wq, q, nullptr, ROWS, DOUT, DIN);
    tf32_gemm<<<dim3(LAT / 128, ROWS / 128), 256>>>(x, Wdkv, lat, nullptr, ROWS, LAT, DIN);
    tf32_gemm<<<dim3(DOUT / 128, ROWS / 128), 256>>>(lat, Wuk, k, nullptr, ROWS, DOUT, LAT);
    tf32_gemm<<<dim3(DOUT / 128, ROWS / 128), 256>>>(lat, Wuv, v, nullptr, ROWS, DOUT, LAT);
    flash_attn_reg<<<dim3(S_ / FBM, B_ * NH), 256, FA_SMEM_BYTES>>>(q, k, v, ctx);
    tf32_gemm<<<dim3(DOUT / 128, ROWS / 128), 256>>>(ctx, Wout, out, bout, ROWS, DOUT, DOUT);
}